// round 8
// baseline (speedup 1.0000x reference)
#include <cuda_runtime.h>
#include <cuda_bf16.h>
#include <math.h>
#include <stdint.h>

#define N_CAP 50048
#define E_CAP 500224
#define NCOL 112

// ---------------- scratch ----------------------------------------------------
__device__ float g_xl[N_CAP * 64];
__device__ float g_xr[N_CAP * 64];
__device__ float g_m1[N_CAP * 4];
__device__ float g_s1[N_CAP * 4];
__device__ float g_num1[N_CAP * 64];
__device__ float g_m2[N_CAP * 2];
__device__ float g_s2[N_CAP * 2];
__device__ float g_num2[N_CAP * 32];
__device__ float g_m3[N_CAP];
__device__ float g_s3[N_CAP];
__device__ float g_num3[N_CAP * 16];
__device__ float g_logits[E_CAP * 4];
__device__ float g_ea23[E_CAP * 48];
__device__ float g_x3[N_CAP * 16];
// fragment-ordered B: [13 kc][2 plane(hi/lo)][14 nt][32 lane][4 u32]
__device__ uint32_t g_Bf[13 * 2 * 14 * 32 * 4];

// ---------------- helpers ----------------------------------------------------
__device__ __forceinline__ float leakyr(float v) { return v > 0.f ? v : 0.2f * v; }
__device__ __forceinline__ float eluf(float v)   { return v > 0.f ? v : (expf(v) - 1.f); }

__device__ __forceinline__ void atomicMaxF(float* a, float v) {
    if (v >= 0.f) atomicMax(reinterpret_cast<int*>(a), __float_as_int(v));
    else          atomicMin(reinterpret_cast<unsigned int*>(a), __float_as_uint(v));
}
__device__ __forceinline__ void red4(float* p, float a, float b, float c, float d) {
    asm volatile("red.global.add.v4.f32 [%0], {%1, %2, %3, %4};"
                 :: "l"(p), "f"(a), "f"(b), "f"(c), "f"(d) : "memory");
}
__device__ __forceinline__ uint32_t smem_u32(const void* p) {
    uint32_t a;
    asm("{ .reg .u64 t; cvta.to.shared.u64 t, %1; cvt.u32.u64 %0, t; }" : "=r"(a) : "l"(p));
    return a;
}
__device__ __forceinline__ void mma_bf16(float* d, uint32_t a0, uint32_t a1,
                                         uint32_t a2, uint32_t a3,
                                         uint32_t b0, uint32_t b1) {
    asm volatile(
        "mma.sync.aligned.m16n8k16.row.col.f32.bf16.bf16.f32 "
        "{%0,%1,%2,%3}, {%4,%5,%6,%7}, {%8,%9}, {%0,%1,%2,%3};"
        : "+f"(d[0]), "+f"(d[1]), "+f"(d[2]), "+f"(d[3])
        : "r"(a0), "r"(a1), "r"(a2), "r"(a3), "r"(b0), "r"(b1));
}
__device__ __forceinline__ void cp16(uint32_t dst_smem, const void* src) {
    asm volatile("cp.async.cg.shared.global [%0], [%1], 16;"
                 :: "r"(dst_smem), "l"(src) : "memory");
}
#define CP_COMMIT()  asm volatile("cp.async.commit_group;" ::: "memory")
#define CP_WAIT(n)   asm volatile("cp.async.wait_group %0;" :: "n"(n) : "memory")

__device__ __forceinline__ void cvtHL(float x0, float x1, uint32_t& h, uint32_t& l) {
    __nv_bfloat16 h0 = __float2bfloat16(x0);
    __nv_bfloat16 h1 = __float2bfloat16(x1);
    __nv_bfloat162 hb(h0, h1);
    h = *reinterpret_cast<uint32_t*>(&hb);
    __nv_bfloat162 lb(__float2bfloat16(x0 - __bfloat162float(h0)),
                      __float2bfloat16(x1 - __bfloat162float(h1)));
    l = *reinterpret_cast<uint32_t*>(&lb);
}

// ---------------- weight prep: fragment-ordered, bf16 hi/lo -------------------
__device__ __forceinline__ float getW(int k, int n,
                                      const float* We1, const float* We2, const float* We3) {
    if (k > 384) return 0.f;
    if (n < 64)  return We1[k * 64 + n];
    if (n < 96)  return We2[k * 32 + (n - 64)];
    return We3[k * 16 + (n - 96)];
}
__global__ void k_prep_w(const float* __restrict__ We1, const float* __restrict__ We2,
                         const float* __restrict__ We3) {
    int idx = blockIdx.x * blockDim.x + threadIdx.x;
    if (idx >= 13 * 2 * 14 * 32 * 4) return;
    int s = idx & 3;
    int r = idx >> 2;
    int lane = r & 31; r >>= 5;
    int nt = r % 14; r /= 14;
    int pl = r & 1;
    int kc = r >> 1;
    int g = lane >> 2, c = lane & 3;
    int n = nt * 8 + g;
    int koff = (s & 1) * 8 + (s >> 1) * 16 + 2 * c;
    int k = kc * 32 + koff;
    float w0 = getW(k, n, We1, We2, We3);
    float w1 = getW(k + 1, n, We1, We2, We3);
    uint32_t h, l;
    cvtHL(w0, w1, h, l);
    g_Bf[idx] = pl ? l : h;
}

// ---------------- layer 1 node projection -----------------------------------
__global__ void k_node1(const int* __restrict__ node_ids,
                        const float* __restrict__ emb,
                        const float* __restrict__ Wl, const float* __restrict__ bl,
                        const float* __restrict__ Wr, const float* __restrict__ br,
                        int n) {
    int node = blockIdx.x;
    if (node >= n) return;
    int c = threadIdx.x;  // 0..63
    __shared__ float sx[32];
    if (c < 32) sx[c] = emb[node_ids[node] * 32 + c];
    __syncthreads();
    float al = bl[c], ar = br[c];
#pragma unroll
    for (int k = 0; k < 32; k++) {
        float xv = sx[k];
        al += xv * Wl[k * 64 + c];
        ar += xv * Wr[k * 64 + c];
    }
    g_xl[node * 64 + c] = al;
    g_xr[node * 64 + c] = ar;
}

__global__ void k_init1(int n) {
    int i = blockIdx.x * blockDim.x + threadIdx.x;
    if (i < n * 64) g_num1[i] = 0.f;
    if (i < n * 4) { g_m1[i] = -INFINITY; g_s1[i] = 0.f; }
}

// ---------------- bf16 mma.sync edge projection (8 warps, 1 tile/warp) --------
// 128 edges/CTA, 256 threads. Warp w owns m16 tile rows [16w, 16w+16).
// A: cp.async raw fp32 (aligned-floor), 2-stage, warp-private rows.
// B: fragment-ordered global -> cp.async 3-stage smem ring (block-shared).
#define A_STRIDE 40
#define A_STAGE_F (128 * A_STRIDE)
#define A_STAGE_B (A_STAGE_F * 4)          // 20480 B
#define B_STAGE_B (2 * 14 * 32 * 16)       // 14336 B
#define SM_B_OFF (2 * A_STAGE_B)           // 40960
#define SM_EP_TOTAL (SM_B_OFF + 3 * B_STAGE_B)  // 83968

__global__ void __launch_bounds__(256, 2) k_edge_mma(
        const float* __restrict__ eattr,
        const int* __restrict__ src, const int* __restrict__ dst,
        const float* __restrict__ att1, int e) {
    extern __shared__ char smem[];
    float* smA = reinterpret_cast<float*>(smem);
    const uint32_t smb = smem_u32(smem);
    const int tid  = threadIdx.x;
    const int w    = tid >> 5;
    const int lane = tid & 31;
    const int g    = lane >> 2;
    const int c    = lane & 3;
    const int eb   = blockIdx.x * 128;
    const int nE   = min(128, e - eb);

    // A-copy assignment: warp w copies its own rows [16w, 16w+16), 2 lanes/row
    const int rowC  = w * 16 + (lane & 15);
    const int halfC = lane >> 4;
    const bool rowCok = rowC < nE;
    const int globC = eb + rowC;
    const int shC   = globC & 3;
    const size_t rowBaseC = (size_t)globC * 385;

#define ISSUE(kc_)                                                            \
    do {                                                                      \
        if (rowCok) {                                                         \
            if ((kc_) == 12) {                                                \
                if (halfC == 0)                                               \
                    smA[((kc_) & 1) * A_STAGE_F + rowC * A_STRIDE + shC] =    \
                        eattr[rowBaseC + 384];                                \
            } else if ((kc_) == 11 && globC == e - 1) {                       \
                if (halfC == 0) {                                             \
                    float* dstf = smA + ((kc_) & 1) * A_STAGE_F + rowC * A_STRIDE; \
                    for (int p = 0; p < 36; p++) {                            \
                        int kf = 352 - shC + p;                               \
                        dstf[p] = (kf <= 384) ? eattr[rowBaseC + kf] : 0.f;   \
                    }                                                         \
                }                                                             \
            } else {                                                          \
                uint32_t dstb = smb + ((kc_) & 1) * A_STAGE_B + rowC * (A_STRIDE * 4); \
                const char* sp = (const char*)eattr +                         \
                                 (((rowBaseC + (kc_) * 32) * 4) & ~(size_t)15); \
                if (halfC == 0) {                                             \
                    _Pragma("unroll")                                         \
                    for (int q = 0; q < 5; q++) cp16(dstb + q * 16, sp + q * 16); \
                } else {                                                      \
                    _Pragma("unroll")                                         \
                    for (int q = 5; q < 9; q++) cp16(dstb + q * 16, sp + q * 16); \
                }                                                             \
            }                                                                 \
        }                                                                     \
        {                                                                     \
            uint32_t bst = smb + SM_B_OFF + ((kc_) % 3) * B_STAGE_B;          \
            const char* bsrc = (const char*)g_Bf + (size_t)(kc_) * B_STAGE_B; \
            for (int i2 = tid; i2 < 896; i2 += 256)                           \
                cp16(bst + i2 * 16, bsrc + i2 * 16);                          \
        }                                                                     \
        CP_COMMIT();                                                          \
    } while (0)

    float D[14][4];
#pragma unroll
    for (int nt = 0; nt < 14; nt++)
#pragma unroll
        for (int q = 0; q < 4; q++) D[nt][q] = 0.f;

    ISSUE(0);
    ISSUE(1);

    const int shF = g & 3;   // alignment shift for fragment rows (row & 3 == g & 3)

#pragma unroll 1
    for (int kc = 0; kc < 13; kc++) {
        if (kc < 12) { CP_WAIT(1); } else { CP_WAIT(0); }
        __syncthreads();

        // ---- A fragments: raw fp32 -> bf16 hi/lo (1 m16 tile) ----
        const float* sAst = smA + (kc & 1) * A_STAGE_F;
        uint32_t aH[2][4], aL[2][4];
        {
            int rA = (w * 16 + g) * A_STRIDE;
            int rB = rA + 8 * A_STRIDE;
#pragma unroll
            for (int k16 = 0; k16 < 2; k16++) {
                int c0 = shF + k16 * 16 + 2 * c;
                int c1 = c0 + 8;
                cvtHL(sAst[rA + c0], sAst[rA + c0 + 1], aH[k16][0], aL[k16][0]);
                cvtHL(sAst[rB + c0], sAst[rB + c0 + 1], aH[k16][1], aL[k16][1]);
                cvtHL(sAst[rA + c1], sAst[rA + c1 + 1], aH[k16][2], aL[k16][2]);
                cvtHL(sAst[rB + c1], sAst[rB + c1 + 1], aH[k16][3], aL[k16][3]);
            }
        }
        __syncwarp();
        if (kc + 2 <= 12) {
            switch (kc + 2) {
                case 2: ISSUE(2); break;   case 3: ISSUE(3); break;
                case 4: ISSUE(4); break;   case 5: ISSUE(5); break;
                case 6: ISSUE(6); break;   case 7: ISSUE(7); break;
                case 8: ISSUE(8); break;   case 9: ISSUE(9); break;
                case 10: ISSUE(10); break; case 11: ISSUE(11); break;
                case 12: ISSUE(12); break;
            }
        }

        // ---- B fragments from smem + MMA ----
        const uint4* sB = reinterpret_cast<const uint4*>(smem + SM_B_OFF + (kc % 3) * B_STAGE_B);
        const uint4* bH = sB + lane;
        const uint4* bL = sB + 14 * 32 + lane;
#pragma unroll
        for (int nt = 0; nt < 14; nt++) {
            uint4 BH = bH[nt * 32];
            uint4 BL = bL[nt * 32];
            mma_bf16(D[nt], aH[0][0], aH[0][1], aH[0][2], aH[0][3], BH.x, BH.y);
            mma_bf16(D[nt], aL[0][0], aL[0][1], aL[0][2], aL[0][3], BH.x, BH.y);
            mma_bf16(D[nt], aH[0][0], aH[0][1], aH[0][2], aH[0][3], BL.x, BL.y);
            mma_bf16(D[nt], aH[1][0], aH[1][1], aH[1][2], aH[1][3], BH.z, BH.w);
            mma_bf16(D[nt], aL[1][0], aL[1][1], aL[1][2], aL[1][3], BH.z, BH.w);
            mma_bf16(D[nt], aH[1][0], aH[1][1], aH[1][2], aH[1][3], BL.z, BL.w);
        }
    }

    // -------- epilogue: fragments -> logits1 + ea23 stores --------
    {
        int rA = w * 16 + g, rB = rA + 8;
        int eeA = eb + rA, eeB = eb + rB;
        bool vA = rA < nE, vB = rB < nE;
        int sA_ = vA ? src[eeA] : 0, dA_ = vA ? dst[eeA] : 0;
        int sB_ = vB ? src[eeB] : 0, dB_ = vB ? dst[eeB] : 0;

#pragma unroll
        for (int h = 0; h < 4; h++) {
            float pA = 0.f, pB = 0.f;
#pragma unroll
            for (int q = 0; q < 2; q++) {
                int nt = 2 * h + q;
                int col = nt * 8 + c * 2;
                float at0 = att1[col], at1 = att1[col + 1];
                float2 xjA = *reinterpret_cast<const float2*>(g_xl + (size_t)sA_ * 64 + col);
                float2 xiA = *reinterpret_cast<const float2*>(g_xr + (size_t)dA_ * 64 + col);
                pA += leakyr(D[nt][0] + xjA.x + xiA.x) * at0
                    + leakyr(D[nt][1] + xjA.y + xiA.y) * at1;
                float2 xjB = *reinterpret_cast<const float2*>(g_xl + (size_t)sB_ * 64 + col);
                float2 xiB = *reinterpret_cast<const float2*>(g_xr + (size_t)dB_ * 64 + col);
                pB += leakyr(D[nt][2] + xjB.x + xiB.x) * at0
                    + leakyr(D[nt][3] + xjB.y + xiB.y) * at1;
            }
            pA += __shfl_xor_sync(0xFFFFFFFFu, pA, 1);
            pA += __shfl_xor_sync(0xFFFFFFFFu, pA, 2);
            pB += __shfl_xor_sync(0xFFFFFFFFu, pB, 1);
            pB += __shfl_xor_sync(0xFFFFFFFFu, pB, 2);
            if (c == 0) {
                if (vA) {
                    g_logits[(size_t)eeA * 4 + h] = pA;
                    atomicMaxF(&g_m1[(size_t)dA_ * 4 + h], pA);
                }
                if (vB) {
                    g_logits[(size_t)eeB * 4 + h] = pB;
                    atomicMaxF(&g_m1[(size_t)dB_ * 4 + h], pB);
                }
            }
        }
#pragma unroll
        for (int nt = 8; nt < 14; nt++) {
            int off = (nt < 12) ? (nt - 8) * 8 + c * 2
                                : 32 + (nt - 12) * 8 + c * 2;
            if (vA) *reinterpret_cast<float2*>(g_ea23 + (size_t)eeA * 48 + off) =
                        make_float2(D[nt][0], D[nt][1]);
            if (vB) *reinterpret_cast<float2*>(g_ea23 + (size_t)eeB * 48 + off) =
                        make_float2(D[nt][2], D[nt][3]);
        }
    }
}

// ---------------- softmax-exp + weighted aggregation (vector red) -----------
__global__ void k_soft1(const int* __restrict__ src, const int* __restrict__ dst, int e) {
    int t = blockIdx.x * blockDim.x + threadIdx.x;
    int ee = t >> 4;
    if (ee >= e) return;
    int q = t & 15, h = q >> 2, c4 = q * 4;
    int s = src[ee], d = dst[ee];
    float ex = expf(g_logits[(size_t)ee * 4 + h] - g_m1[(size_t)d * 4 + h]);
    if ((q & 3) == 0) atomicAdd(&g_s1[(size_t)d * 4 + h], ex);
    float4 x = *reinterpret_cast<const float4*>(g_xl + (size_t)s * 64 + c4);
    red4(g_num1 + (size_t)d * 64 + c4, ex * x.x, ex * x.y, ex * x.z, ex * x.w);
}

__global__ void k_soft2(const int* __restrict__ src, const int* __restrict__ dst, int e) {
    int t = blockIdx.x * blockDim.x + threadIdx.x;
    int ee = t >> 3;
    if (ee >= e) return;
    int q = t & 7, h = q >> 2, c4 = q * 4;
    int s = src[ee], d = dst[ee];
    float ex = expf(g_logits[(size_t)ee * 2 + h] - g_m2[(size_t)d * 2 + h]);
    if ((q & 3) == 0) atomicAdd(&g_s2[(size_t)d * 2 + h], ex);
    float4 x = *reinterpret_cast<const float4*>(g_xl + (size_t)s * 32 + c4);
    red4(g_num2 + (size_t)d * 32 + c4, ex * x.x, ex * x.y, ex * x.z, ex * x.w);
}

__global__ void k_soft3(const int* __restrict__ src, const int* __restrict__ dst, int e) {
    int t = blockIdx.x * blockDim.x + threadIdx.x;
    int ee = t >> 2;
    if (ee >= e) return;
    int q = t & 3, c4 = q * 4;
    int s = src[ee], d = dst[ee];
    float ex = expf(g_logits[ee] - g_m3[d]);
    if (q == 0) atomicAdd(&g_s3[d], ex);
    float4 x = *reinterpret_cast<const float4*>(g_xl + (size_t)s * 16 + c4);
    red4(g_num3 + (size_t)d * 16 + c4, ex * x.x, ex * x.y, ex * x.z, ex * x.w);
}

// ---------------- finish layer1 + project layer2 -----------------------------
__global__ void k_node_fin1(const float* __restrict__ bias1,
                            const float* __restrict__ Wl2, const float* __restrict__ bl2,
                            const float* __restrict__ Wr2, const float* __restrict__ br2,
                            int n) {
    int node = blockIdx.x;
    if (node >= n) return;
    int c = threadIdx.x;  // 0..63
    __shared__ float sx[64];
    float v = g_num1[(size_t)node * 64 + c] / (g_s1[(size_t)node * 4 + (c >> 4)] + 1e-16f) + bias1[c];
    sx[c] = eluf(v);
    __syncthreads();
    if (c < 32) {
        float a = bl2[c];
#pragma unroll
        for (int k = 0; k < 64; k++) a += sx[k] * Wl2[k * 32 + c];
        g_xl[(size_t)node * 32 + c] = a;
        g_num2[(size_t)node * 32 + c] = 0.f;
    } else {
        int c2 = c - 32;
        float a = br2[c2];
#pragma unroll
        for (int k = 0; k < 64; k++) a += sx[k] * Wr2[k * 32 + c2];
        g_xr[(size_t)node * 32 + c2] = a;
    }
    if (c < 2) { g_m2[(size_t)node * 2 + c] = -INFINITY; g_s2[(size_t)node * 2 + c] = 0.f; }
}

// ---------------- layer-2 logits ---------------------------------------------
__global__ void k_edge_logits2(const int* __restrict__ src, const int* __restrict__ dst,
                               const float* __restrict__ att2, int e) {
    int ee = blockIdx.x * 8 + (threadIdx.x >> 5);
    if (ee >= e) return;
    int c = threadIdx.x & 31;
    int s = src[ee], d = dst[ee];
    float ev = leakyr(g_xl[(size_t)s * 32 + c] + g_xr[(size_t)d * 32 + c] + g_ea23[(size_t)ee * 48 + c]);
    float p = ev * att2[c];
    p += __shfl_xor_sync(0xFFFFFFFFu, p, 8);
    p += __shfl_xor_sync(0xFFFFFFFFu, p, 4);
    p += __shfl_xor_sync(0xFFFFFFFFu, p, 2);
    p += __shfl_xor_sync(0xFFFFFFFFu, p, 1);
    if ((c & 15) == 0) {
        int h = c >> 4;
        g_logits[(size_t)ee * 2 + h] = p;
        atomicMaxF(&g_m2[(size_t)d * 2 + h], p);
    }
}

// ---------------- finish layer2 + project layer3 ------------------------------
__global__ void k_node_fin2(const float* __restrict__ bias2,
                            const float* __restrict__ Wl3, const float* __restrict__ bl3,
                            const float* __restrict__ Wr3, const float* __restrict__ br3,
                            int n) {
    int node = blockIdx.x;
    if (node >= n) return;
    int c = threadIdx.x;  // 0..31
    __shared__ float sx[32];
    float v = g_num2[(size_t)node * 32 + c] / (g_s2[(size_t)node * 2 + (c >> 4)] + 1e-16f) + bias2[c];
    sx[c] = eluf(v);
    __syncthreads();
    if (c < 16) {
        float a = bl3[c];
#pragma unroll
        for (int k = 0; k < 32; k++) a += sx[k] * Wl3[k * 16 + c];
        g_xl[(size_t)node * 16 + c] = a;
        g_num3[(size_t)node * 16 + c] = 0.f;
    } else {
        int c2 = c - 16;
        float a = br3[c2];
#pragma unroll
        for (int k = 0; k < 32; k++) a += sx[k] * Wr3[k * 16 + c2];
        g_xr[(size_t)node * 16 + c2] = a;
    }
    if (c == 0) { g_m3[node] = -INFINITY; g_s3[node] = 0.f; }
}

// ---------------- layer-3 logits ----------------------------------------------
__global__ void k_edge_logits3(const int* __restrict__ src, const int* __restrict__ dst,
                               const float* __restrict__ att3, int e) {
    int ee = blockIdx.x * 8 + (threadIdx.x >> 4);
    int c = threadIdx.x & 15;
    bool ok = ee < e;
    int s = ok ? src[ee] : 0, d = ok ? dst[ee] : 0;
    float ev = ok ? leakyr(g_xl[(size_t)s * 16 + c] + g_xr[(size_t)d * 16 + c] + g_ea23[(size_t)ee * 48 + 32 + c]) : 0.f;
    float p = ev * att3[c];
    p += __shfl_xor_sync(0xFFFFFFFFu, p, 8);
    p += __shfl_xor_sync(0xFFFFFFFFu, p, 4);
    p += __shfl_xor_sync(0xFFFFFFFFu, p, 2);
    p += __shfl_xor_sync(0xFFFFFFFFu, p, 1);
    if (ok && c == 0) {
        g_logits[ee] = p;
        atomicMaxF(&g_m3[d], p);
    }
}

// ---------------- finish layer3 ------------------------------------------------
__global__ void k_node_fin3(const float* __restrict__ bias3, int n) {
    int i = blockIdx.x * blockDim.x + threadIdx.x;
    if (i >= n * 16) return;
    g_x3[i] = g_num3[i] / (g_s3[i >> 4] + 1e-16f) + bias3[i & 15];
}

// ---------------- edge MLP: 8 edges per 128-thread block ----------------------
__global__ void k_mlp(const int* __restrict__ src, const int* __restrict__ dst,
                      const float* __restrict__ W1, const float* __restrict__ b1,
                      const float* __restrict__ W2, const float* __restrict__ b2,
                      const float* __restrict__ W3, const float* __restrict__ b3,
                      float* __restrict__ out, int e) {
    __shared__ float h0[8][32], h1[8][64], h2[8][32];
    int tid = threadIdx.x;
    int eb = blockIdx.x * 8;

    for (int i = tid; i < 256; i += 128) {
        int le = i >> 5, j = i & 31;
        int ee = eb + le;
        if (ee < e) {
            int nn = (j < 16) ? src[ee] : dst[ee];
            h0[le][j] = g_x3[(size_t)nn * 16 + (j & 15)];
        }
    }
    __syncthreads();

    {
        int j = tid & 63, g = tid >> 6;
        float a0 = b1[j], a1 = a0, a2 = a0, a3 = a0;
        const float* r0 = h0[g * 4 + 0];
        const float* r1 = h0[g * 4 + 1];
        const float* r2 = h0[g * 4 + 2];
        const float* r3 = h0[g * 4 + 3];
#pragma unroll
        for (int k = 0; k < 32; k++) {
            float w = W1[k * 64 + j];
            a0 += r0[k] * w; a1 += r1[k] * w; a2 += r2[k] * w; a3 += r3[k] * w;
        }
        h1[g * 4 + 0][j] = fmaxf(a0, 0.f);
        h1[g * 4 + 1][j] = fmaxf(a1, 0.f);
        h1[g * 4 + 2][j] = fmaxf(a2, 0.f);
        h1[g * 4 + 3][j] = fmaxf(a3, 0.f);
    }
    __syncthreads();

    {
        int j = tid & 31, g = tid >> 5;
        float a0 = b2[j], a1 = a0;
        const float* r0 = h1[g * 2 + 0];
        const float* r1 = h1[g * 2 + 1];
#pragma unroll
        for (int k = 0; k < 64; k++) {
            float w = W2[k * 32 + j];
            a0 += r0[k] * w; a1 += r1[k] * w;
        }
        h2[g * 2 + 0][j] = fmaxf(a0, 0.f);
        h2[g * 2 + 1][j] = fmaxf(a1, 0.f);
    }
    __syncthreads();

    {
        int e8 = tid >> 4, c = tid & 15;
        float p = h2[e8][c] * W3[c] + h2[e8][c + 16] * W3[c + 16];
        p += __shfl_xor_sync(0xFFFFFFFFu, p, 8);
        p += __shfl_xor_sync(0xFFFFFFFFu, p, 4);
        p += __shfl_xor_sync(0xFFFFFFFFu, p, 2);
        p += __shfl_xor_sync(0xFFFFFFFFu, p, 1);
        int ee = eb + e8;
        if (c == 0 && ee < e) out[ee] = p + b3[0];
    }
}

// ---------------- launch --------------------------------------------------------
extern "C" void kernel_launch(void* const* d_in, const int* in_sizes, int n_in,
                              void* d_out, int out_size) {
    const int*   node_ids = (const int*)  d_in[0];
    const int*   eidx     = (const int*)  d_in[1];
    const float* eattr    = (const float*)d_in[2];
    const float* emb      = (const float*)d_in[3];
    const float* l1_Wl   = (const float*)d_in[4];
    const float* l1_bl   = (const float*)d_in[5];
    const float* l1_Wr   = (const float*)d_in[6];
    const float* l1_br   = (const float*)d_in[7];
    const float* l1_We   = (const float*)d_in[8];
    const float* l1_att  = (const float*)d_in[9];
    const float* l1_bias = (const float*)d_in[10];
    const float* l2_Wl   = (const float*)d_in[11];
    const float* l2_bl   = (const float*)d_in[12];
    const float* l2_Wr   = (const float*)d_in[13];
    const float* l2_br   = (const float*)d_in[14];
    const float* l2_We   = (const float*)d_in[15];
    const float* l2_att  = (const float*)d_in[16];
    const float* l2_bias = (const float*)d_in[17];
    const float* l3_Wl   = (const float*)d_in[18];
    const float* l3_bl   = (const float*)d_in[19];
    const float* l3_Wr   = (const float*)d_in[20];
    const float* l3_br   = (const float*)d_in[21];
    const float* l3_We   = (const float*)d_in[22];
    const float* l3_att  = (const float*)d_in[23];
    const float* l3_bias = (const float*)d_in[24];
    const float* mlp_W1  = (const float*)d_in[25];
    const float* mlp_b1  = (const float*)d_in[26];
    const float* mlp_W2  = (const float*)d_in[27];
    const float* mlp_b2  = (const float*)d_in[28];
    const float* mlp_W3  = (const float*)d_in[29];
    const float* mlp_b3  = (const float*)d_in[30];

    int n = in_sizes[0];
    int e = in_sizes[1] / 2;
    const int* src = eidx;
    const int* dst = eidx + e;
    float* out = (float*)d_out;

    static bool attr_set = false;
    if (!attr_set) {
        cudaFuncSetAttribute(k_edge_mma, cudaFuncAttributeMaxDynamicSharedMemorySize, SM_EP_TOTAL);
        attr_set = true;
    }

    // ---- prep + layer 1 (edge GEMM is launch #4 for ncu visibility) ----
    k_prep_w<<<(13 * 2 * 14 * 32 * 4 + 255) / 256, 256>>>(l1_We, l2_We, l3_We);
    k_node1<<<n, 64>>>(node_ids, emb, l1_Wl, l1_bl, l1_Wr, l1_br, n);
    k_init1<<<(n * 64 + 255) / 256, 256>>>(n);
    k_edge_mma<<<(e + 127) / 128, 256, SM_EP_TOTAL>>>(eattr, src, dst, l1_att, e);
    k_soft1<<<(e * 16 + 255) / 256, 256>>>(src, dst, e);
    k_node_fin1<<<n, 64>>>(l1_bias, l2_Wl, l2_bl, l2_Wr, l2_br, n);

    // ---- layer 2 ----
    k_edge_logits2<<<(e + 7) / 8, 256>>>(src, dst, l2_att, e);
    k_soft2<<<(e * 8 + 255) / 256, 256>>>(src, dst, e);
    k_node_fin2<<<n, 32>>>(l2_bias, l3_Wl, l3_bl, l3_Wr, l3_br, n);

    // ---- layer 3 ----
    k_edge_logits3<<<(e + 7) / 8, 128>>>(src, dst, l3_att, e);
    k_soft3<<<(e * 4 + 255) / 256, 256>>>(src, dst, e);
    k_node_fin3<<<(n * 16 + 255) / 256, 256>>>(l3_bias, n);

    // ---- edge MLP ----
    k_mlp<<<(e + 7) / 8, 128>>>(src, dst, mlp_W1, mlp_b1, mlp_W2, mlp_b2,
                                mlp_W3, mlp_b3, out, e);
}

// round 9
// speedup vs baseline: 1.1822x; 1.1822x over previous
#include <cuda_runtime.h>
#include <cuda_bf16.h>
#include <math.h>
#include <stdint.h>

#define N_CAP 50048
#define E_CAP 500224
#define KPAD 416
#define NCOL 112

// ---------------- scratch ----------------------------------------------------
__device__ float g_xl[N_CAP * 64];
__device__ float g_xr[N_CAP * 64];
__device__ float g_s1[N_CAP * 4];
__device__ float g_num1[N_CAP * 64];
__device__ float g_s2[N_CAP * 2];
__device__ float g_num2[N_CAP * 32];
__device__ float g_s3[N_CAP];
__device__ float g_num3[N_CAP * 16];
__device__ float g_logits[E_CAP * 4];
__device__ float g_ea23[E_CAP * 48];
__device__ float g_x3[N_CAP * 16];
__device__ __nv_bfloat16 g_Bh[NCOL * KPAD];  // [112][416] row-major (n-major)
__device__ __nv_bfloat16 g_Bl[NCOL * KPAD];

// ---------------- helpers ----------------------------------------------------
__device__ __forceinline__ float leakyr(float v) { return v > 0.f ? v : 0.2f * v; }
__device__ __forceinline__ float eluf(float v)   { return v > 0.f ? v : (expf(v) - 1.f); }

__device__ __forceinline__ void red4(float* p, float a, float b, float c, float d) {
    asm volatile("red.global.add.v4.f32 [%0], {%1, %2, %3, %4};"
                 :: "l"(p), "f"(a), "f"(b), "f"(c), "f"(d) : "memory");
}
__device__ __forceinline__ uint32_t smem_u32(const void* p) {
    uint32_t a;
    asm("{ .reg .u64 t; cvta.to.shared.u64 t, %1; cvt.u32.u64 %0, t; }" : "=r"(a) : "l"(p));
    return a;
}
__device__ __forceinline__ void mma_bf16(float* d, uint32_t a0, uint32_t a1,
                                         uint32_t a2, uint32_t a3,
                                         uint32_t b0, uint32_t b1) {
    asm volatile(
        "mma.sync.aligned.m16n8k16.row.col.f32.bf16.bf16.f32 "
        "{%0,%1,%2,%3}, {%4,%5,%6,%7}, {%8,%9}, {%0,%1,%2,%3};"
        : "+f"(d[0]), "+f"(d[1]), "+f"(d[2]), "+f"(d[3])
        : "r"(a0), "r"(a1), "r"(a2), "r"(a3), "r"(b0), "r"(b1));
}
__device__ __forceinline__ void cp16(uint32_t dst_smem, const void* src) {
    asm volatile("cp.async.cg.shared.global [%0], [%1], 16;"
                 :: "r"(dst_smem), "l"(src) : "memory");
}
#define CP_COMMIT()  asm volatile("cp.async.commit_group;" ::: "memory")
#define CP_WAIT(n)   asm volatile("cp.async.wait_group %0;" :: "n"(n) : "memory")

__device__ __forceinline__ void cvtHL(float x0, float x1, uint32_t& h, uint32_t& l) {
    __nv_bfloat16 h0 = __float2bfloat16(x0);
    __nv_bfloat16 h1 = __float2bfloat16(x1);
    __nv_bfloat162 hb(h0, h1);
    h = *reinterpret_cast<uint32_t*>(&hb);
    __nv_bfloat162 lb(__float2bfloat16(x0 - __bfloat162float(h0)),
                      __float2bfloat16(x1 - __bfloat162float(h1)));
    l = *reinterpret_cast<uint32_t*>(&lb);
}

// ---------------- weight prep: combined, padded, bf16 hi/lo, [n][k] ----------
__global__ void k_prep_w(const float* __restrict__ We1, const float* __restrict__ We2,
                         const float* __restrict__ We3) {
    int idx = blockIdx.x * blockDim.x + threadIdx.x;
    if (idx >= NCOL * KPAD) return;
    int j = idx / KPAD, k = idx - j * KPAD;
    float w = 0.f;
    if (k < 385) {
        if (j < 64)      w = We1[k * 64 + j];
        else if (j < 96) w = We2[k * 32 + (j - 64)];
        else             w = We3[k * 16 + (j - 96)];
    }
    __nv_bfloat16 h = __float2bfloat16(w);
    __nv_bfloat16 l = __float2bfloat16(w - __bfloat162float(h));
    g_Bh[idx] = h;
    g_Bl[idx] = l;
}

// ---------------- layer 1 node projection -----------------------------------
__global__ void k_node1(const int* __restrict__ node_ids,
                        const float* __restrict__ emb,
                        const float* __restrict__ Wl, const float* __restrict__ bl,
                        const float* __restrict__ Wr, const float* __restrict__ br,
                        int n) {
    int node = blockIdx.x;
    if (node >= n) return;
    int c = threadIdx.x;  // 0..63
    __shared__ float sx[32];
    if (c < 32) sx[c] = emb[node_ids[node] * 32 + c];
    __syncthreads();
    float al = bl[c], ar = br[c];
#pragma unroll
    for (int k = 0; k < 32; k++) {
        float xv = sx[k];
        al += xv * Wl[k * 64 + c];
        ar += xv * Wr[k * 64 + c];
    }
    g_xl[node * 64 + c] = al;
    g_xr[node * 64 + c] = ar;
}

__global__ void k_init1(int n) {
    int i = blockIdx.x * blockDim.x + threadIdx.x;
    if (i < n * 64) g_num1[i] = 0.f;
    if (i < n * 4) g_s1[i] = 0.f;
}

// ---------------- bf16 mma.sync edge projection (R5 config) -------------------
#define SA_STRIDE 36
#define SB_STRIDE 40
#define SM_AH 0
#define SM_AL (128 * SA_STRIDE * 2)
#define SM_BH (SM_AL + 128 * SA_STRIDE * 2)
#define SM_BL (SM_BH + 2 * 112 * SB_STRIDE * 2)
#define SM_EP_TOTAL (SM_BL + 2 * 112 * SB_STRIDE * 2)

__global__ void __launch_bounds__(128, 2) k_edge_mma(
        const float* __restrict__ eattr,
        const int* __restrict__ src, const int* __restrict__ dst,
        const float* __restrict__ att1, int e) {
    extern __shared__ char smem[];
    __nv_bfloat16* sAh = reinterpret_cast<__nv_bfloat16*>(smem + SM_AH);
    __nv_bfloat16* sAl = reinterpret_cast<__nv_bfloat16*>(smem + SM_AL);
    const uint32_t sBh_u = smem_u32(smem + SM_BH);
    const uint32_t sBl_u = smem_u32(smem + SM_BL);

    const int tid  = threadIdx.x;
    const int w    = tid >> 5;
    const int lane = tid & 31;
    const int g    = lane >> 2;
    const int c    = lane & 3;
    const int eb   = blockIdx.x * 128;
    const int nE   = min(128, e - eb);

    float D[2][14][4];
#pragma unroll
    for (int tt = 0; tt < 2; tt++)
#pragma unroll
        for (int nt = 0; nt < 14; nt++)
#pragma unroll
            for (int q = 0; q < 4; q++) D[tt][nt][q] = 0.f;

    float aR[32];

#define LOAD_A(kc_)                                                          \
    {                                                                        \
        int k0 = (kc_) * 32;                                                 \
        _Pragma("unroll")                                                    \
        for (int it = 0; it < 16; it++) {                                    \
            int p = it * 128 + tid;                                          \
            int row = p >> 4, cp = p & 15;                                   \
            int col = k0 + cp * 2;                                           \
            float v0 = 0.f, v1 = 0.f;                                        \
            if (row < nE) {                                                  \
                const float* rp = eattr + (size_t)(eb + row) * 385;          \
                if (col < 385)     v0 = rp[col];                             \
                if (col + 1 < 385) v1 = rp[col + 1];                         \
            }                                                                \
            aR[2 * it] = v0; aR[2 * it + 1] = v1;                            \
        }                                                                    \
    }

#define STORE_A()                                                            \
    {                                                                        \
        _Pragma("unroll")                                                    \
        for (int it = 0; it < 16; it++) {                                    \
            int p = it * 128 + tid;                                          \
            int row = p >> 4, cp = p & 15;                                   \
            float v0 = aR[2 * it], v1 = aR[2 * it + 1];                      \
            __nv_bfloat16 h0 = __float2bfloat16(v0);                         \
            __nv_bfloat16 h1 = __float2bfloat16(v1);                         \
            __nv_bfloat16 l0 = __float2bfloat16(v0 - __bfloat162float(h0));  \
            __nv_bfloat16 l1 = __float2bfloat16(v1 - __bfloat162float(h1));  \
            int o = row * SA_STRIDE + cp * 2;                                \
            *reinterpret_cast<__nv_bfloat162*>(sAh + o) = __nv_bfloat162(h0, h1); \
            *reinterpret_cast<__nv_bfloat162*>(sAl + o) = __nv_bfloat162(l0, l1); \
        }                                                                    \
    }

#define CA_B(kc_, buf_)                                                      \
    {                                                                        \
        const char* bh = reinterpret_cast<const char*>(g_Bh);                \
        const char* bl = reinterpret_cast<const char*>(g_Bl);                \
        int koff = (kc_) * 64;                                               \
        uint32_t dsth = sBh_u + (buf_) * 112 * SB_STRIDE * 2;                \
        uint32_t dstl = sBl_u + (buf_) * 112 * SB_STRIDE * 2;                \
        for (int i = tid; i < 448; i += 128) {                               \
            int row = i >> 2, q = i & 3;                                     \
            cp16(dsth + row * (SB_STRIDE * 2) + q * 16,                      \
                 bh + (size_t)row * (KPAD * 2) + koff + q * 16);             \
            cp16(dstl + row * (SB_STRIDE * 2) + q * 16,                      \
                 bl + (size_t)row * (KPAD * 2) + koff + q * 16);             \
        }                                                                    \
    }

    LOAD_A(0);
    CA_B(0, 0);
    CP_COMMIT();

    for (int kc = 0; kc < 13; kc++) {
        __syncthreads();
        STORE_A();
        if (kc < 12) {
            LOAD_A(kc + 1);
            CA_B(kc + 1, (kc + 1) & 1);
            CP_COMMIT();
            CP_WAIT(1);
        } else {
            CP_WAIT(0);
        }
        __syncthreads();

        const __nv_bfloat16* bhp = reinterpret_cast<const __nv_bfloat16*>(smem + SM_BH)
                                   + (kc & 1) * 112 * SB_STRIDE;
        const __nv_bfloat16* blp = reinterpret_cast<const __nv_bfloat16*>(smem + SM_BL)
                                   + (kc & 1) * 112 * SB_STRIDE;
#pragma unroll
        for (int k16 = 0; k16 < 2; k16++) {
            int kb = k16 * 16;
            uint32_t ah[2][4], al_[2][4];
#pragma unroll
            for (int tt = 0; tt < 2; tt++) {
                int m0 = w * 32 + tt * 16;
                int rA = (m0 + g) * SA_STRIDE, rB = (m0 + g + 8) * SA_STRIDE;
                int c0 = kb + 2 * c, c1 = kb + 2 * c + 8;
                ah[tt][0] = *reinterpret_cast<const uint32_t*>(sAh + rA + c0);
                ah[tt][1] = *reinterpret_cast<const uint32_t*>(sAh + rB + c0);
                ah[tt][2] = *reinterpret_cast<const uint32_t*>(sAh + rA + c1);
                ah[tt][3] = *reinterpret_cast<const uint32_t*>(sAh + rB + c1);
                al_[tt][0] = *reinterpret_cast<const uint32_t*>(sAl + rA + c0);
                al_[tt][1] = *reinterpret_cast<const uint32_t*>(sAl + rB + c0);
                al_[tt][2] = *reinterpret_cast<const uint32_t*>(sAl + rA + c1);
                al_[tt][3] = *reinterpret_cast<const uint32_t*>(sAl + rB + c1);
            }
#pragma unroll
            for (int nt = 0; nt < 14; nt++) {
                int n = nt * 8 + g;
                int c0 = kb + 2 * c, c1 = kb + 2 * c + 8;
                uint32_t bh0 = *reinterpret_cast<const uint32_t*>(bhp + n * SB_STRIDE + c0);
                uint32_t bh1 = *reinterpret_cast<const uint32_t*>(bhp + n * SB_STRIDE + c1);
                uint32_t bl0 = *reinterpret_cast<const uint32_t*>(blp + n * SB_STRIDE + c0);
                uint32_t bl1 = *reinterpret_cast<const uint32_t*>(blp + n * SB_STRIDE + c1);
#pragma unroll
                for (int tt = 0; tt < 2; tt++) {
                    mma_bf16(D[tt][nt], ah[tt][0], ah[tt][1], ah[tt][2], ah[tt][3], bh0, bh1);
                    mma_bf16(D[tt][nt], al_[tt][0], al_[tt][1], al_[tt][2], al_[tt][3], bh0, bh1);
                    mma_bf16(D[tt][nt], ah[tt][0], ah[tt][1], ah[tt][2], ah[tt][3], bl0, bl1);
                }
            }
        }
    }

    // -------- epilogue: logits1 (no max pass) + ea23 stores --------
#pragma unroll
    for (int tt = 0; tt < 2; tt++) {
        int m0 = w * 32 + tt * 16;
        int rA = m0 + g, rB = m0 + g + 8;
        int eeA = eb + rA, eeB = eb + rB;
        bool vA = rA < nE, vB = rB < nE;
        int sA_ = vA ? src[eeA] : 0, dA_ = vA ? dst[eeA] : 0;
        int sB_ = vB ? src[eeB] : 0, dB_ = vB ? dst[eeB] : 0;

#pragma unroll
        for (int h = 0; h < 4; h++) {
            float pA = 0.f, pB = 0.f;
#pragma unroll
            for (int q = 0; q < 2; q++) {
                int nt = 2 * h + q;
                int col = nt * 8 + c * 2;
                float at0 = att1[col], at1 = att1[col + 1];
                float2 xjA = *reinterpret_cast<const float2*>(g_xl + (size_t)sA_ * 64 + col);
                float2 xiA = *reinterpret_cast<const float2*>(g_xr + (size_t)dA_ * 64 + col);
                pA += leakyr(D[tt][nt][0] + xjA.x + xiA.x) * at0
                    + leakyr(D[tt][nt][1] + xjA.y + xiA.y) * at1;
                float2 xjB = *reinterpret_cast<const float2*>(g_xl + (size_t)sB_ * 64 + col);
                float2 xiB = *reinterpret_cast<const float2*>(g_xr + (size_t)dB_ * 64 + col);
                pB += leakyr(D[tt][nt][2] + xjB.x + xiB.x) * at0
                    + leakyr(D[tt][nt][3] + xjB.y + xiB.y) * at1;
            }
            pA += __shfl_xor_sync(0xFFFFFFFFu, pA, 1);
            pA += __shfl_xor_sync(0xFFFFFFFFu, pA, 2);
            pB += __shfl_xor_sync(0xFFFFFFFFu, pB, 1);
            pB += __shfl_xor_sync(0xFFFFFFFFu, pB, 2);
            if (c == 0) {
                if (vA) g_logits[(size_t)eeA * 4 + h] = pA;
                if (vB) g_logits[(size_t)eeB * 4 + h] = pB;
            }
        }
#pragma unroll
        for (int nt = 8; nt < 14; nt++) {
            int off = (nt < 12) ? (nt - 8) * 8 + c * 2
                                : 32 + (nt - 12) * 8 + c * 2;
            if (vA) *reinterpret_cast<float2*>(g_ea23 + (size_t)eeA * 48 + off) =
                        make_float2(D[tt][nt][0], D[tt][nt][1]);
            if (vB) *reinterpret_cast<float2*>(g_ea23 + (size_t)eeB * 48 + off) =
                        make_float2(D[tt][nt][2], D[tt][nt][3]);
        }
    }
}

// ---------------- softmax-exp + weighted aggregation (no max pass) ----------
__global__ void k_soft1(const int* __restrict__ src, const int* __restrict__ dst, int e) {
    int t = blockIdx.x * blockDim.x + threadIdx.x;
    int ee = t >> 4;
    if (ee >= e) return;
    int q = t & 15, h = q >> 2, c4 = q * 4;
    int s = src[ee], d = dst[ee];
    float ex = expf(g_logits[(size_t)ee * 4 + h]);
    if ((q & 3) == 0) atomicAdd(&g_s1[(size_t)d * 4 + h], ex);
    float4 x = *reinterpret_cast<const float4*>(g_xl + (size_t)s * 64 + c4);
    red4(g_num1 + (size_t)d * 64 + c4, ex * x.x, ex * x.y, ex * x.z, ex * x.w);
}

__global__ void k_soft2(const int* __restrict__ src, const int* __restrict__ dst, int e) {
    int t = blockIdx.x * blockDim.x + threadIdx.x;
    int ee = t >> 3;
    if (ee >= e) return;
    int q = t & 7, h = q >> 2, c4 = q * 4;
    int s = src[ee], d = dst[ee];
    float ex = expf(g_logits[(size_t)ee * 2 + h]);
    if ((q & 3) == 0) atomicAdd(&g_s2[(size_t)d * 2 + h], ex);
    float4 x = *reinterpret_cast<const float4*>(g_xl + (size_t)s * 32 + c4);
    red4(g_num2 + (size_t)d * 32 + c4, ex * x.x, ex * x.y, ex * x.z, ex * x.w);
}

__global__ void k_soft3(const int* __restrict__ src, const int* __restrict__ dst, int e) {
    int t = blockIdx.x * blockDim.x + threadIdx.x;
    int ee = t >> 2;
    if (ee >= e) return;
    int q = t & 3, c4 = q * 4;
    int s = src[ee], d = dst[ee];
    float ex = expf(g_logits[ee]);
    if (q == 0) atomicAdd(&g_s3[d], ex);
    float4 x = *reinterpret_cast<const float4*>(g_xl + (size_t)s * 16 + c4);
    red4(g_num3 + (size_t)d * 16 + c4, ex * x.x, ex * x.y, ex * x.z, ex * x.w);
}

// ---------------- finish layer1 + project layer2 (16 nodes/block) ------------
__global__ void __launch_bounds__(256) k_node_fin1(
        const float* __restrict__ bias1,
        const float* __restrict__ Wl2, const float* __restrict__ bl2,
        const float* __restrict__ Wr2, const float* __restrict__ br2, int n) {
    __shared__ float sx[16][65];
    int tid = threadIdx.x;
    int nb = blockIdx.x * 16;
#pragma unroll
    for (int i = 0; i < 4; i++) {
        int o = i * 256 + tid;
        int ln = o >> 6, cc = o & 63;
        int node = nb + ln;
        float v = 0.f;
        if (node < n)
            v = g_num1[(size_t)node * 64 + cc] / (g_s1[(size_t)node * 4 + (cc >> 4)] + 1e-16f) + bias1[cc];
        sx[ln][cc] = eluf(v);
    }
    __syncthreads();
    int c = tid & 63, ng = tid >> 6;  // 4 groups of 4 nodes
    const float* W  = (c < 32) ? Wl2 : Wr2;
    const float* bb = (c < 32) ? bl2 : br2;
    int c2 = c & 31;
    float a[4];
#pragma unroll
    for (int r = 0; r < 4; r++) a[r] = bb[c2];
    for (int k = 0; k < 64; k++) {
        float wv = W[k * 32 + c2];
#pragma unroll
        for (int r = 0; r < 4; r++) a[r] += sx[ng * 4 + r][k] * wv;
    }
#pragma unroll
    for (int r = 0; r < 4; r++) {
        int node = nb + ng * 4 + r;
        if (node < n) {
            if (c < 32) { g_xl[(size_t)node * 32 + c2] = a[r]; g_num2[(size_t)node * 32 + c2] = 0.f; }
            else          g_xr[(size_t)node * 32 + c2] = a[r];
        }
    }
    if (tid < 32) {
        int node = nb + (tid >> 1);
        if (node < n) g_s2[(size_t)node * 2 + (tid & 1)] = 0.f;
    }
}

// ---------------- layer-2 logits ---------------------------------------------
__global__ void k_edge_logits2(const int* __restrict__ src, const int* __restrict__ dst,
                               const float* __restrict__ att2, int e) {
    int ee = blockIdx.x * 8 + (threadIdx.x >> 5);
    if (ee >= e) return;
    int c = threadIdx.x & 31;
    int s = src[ee], d = dst[ee];
    float ev = leakyr(g_xl[(size_t)s * 32 + c] + g_xr[(size_t)d * 32 + c] + g_ea23[(size_t)ee * 48 + c]);
    float p = ev * att2[c];
    p += __shfl_xor_sync(0xFFFFFFFFu, p, 8);
    p += __shfl_xor_sync(0xFFFFFFFFu, p, 4);
    p += __shfl_xor_sync(0xFFFFFFFFu, p, 2);
    p += __shfl_xor_sync(0xFFFFFFFFu, p, 1);
    if ((c & 15) == 0) g_logits[(size_t)ee * 2 + (c >> 4)] = p;
}

// ---------------- finish layer2 + project layer3 (16 nodes/block) ------------
__global__ void __launch_bounds__(256) k_node_fin2(
        const float* __restrict__ bias2,
        const float* __restrict__ Wl3, const float* __restrict__ bl3,
        const float* __restrict__ Wr3, const float* __restrict__ br3, int n) {
    __shared__ float sx[16][33];
    int tid = threadIdx.x;
    int nb = blockIdx.x * 16;
#pragma unroll
    for (int i = 0; i < 2; i++) {
        int o = i * 256 + tid;
        int ln = o >> 5, cc = o & 31;
        int node = nb + ln;
        float v = 0.f;
        if (node < n)
            v = g_num2[(size_t)node * 32 + cc] / (g_s2[(size_t)node * 2 + (cc >> 4)] + 1e-16f) + bias2[cc];
        sx[ln][cc] = eluf(v);
    }
    __syncthreads();
    int c = tid & 31, ng = tid >> 5;  // 8 groups of 2 nodes
    const float* W  = (c < 16) ? Wl3 : Wr3;
    const float* bb = (c < 16) ? bl3 : br3;
    int c2 = c & 15;
    float a[2];
    a[0] = bb[c2]; a[1] = bb[c2];
    for (int k = 0; k < 32; k++) {
        float wv = W[k * 16 + c2];
        a[0] += sx[ng * 2 + 0][k] * wv;
        a[1] += sx[ng * 2 + 1][k] * wv;
    }
#pragma unroll
    for (int r = 0; r < 2; r++) {
        int node = nb + ng * 2 + r;
        if (node < n) {
            if (c < 16) { g_xl[(size_t)node * 16 + c2] = a[r]; g_num3[(size_t)node * 16 + c2] = 0.f; }
            else          g_xr[(size_t)node * 16 + c2] = a[r];
        }
    }
    if (tid < 16) {
        int node = nb + tid;
        if (node < n) g_s3[node] = 0.f;
    }
}

// ---------------- layer-3 logits ----------------------------------------------
__global__ void k_edge_logits3(const int* __restrict__ src, const int* __restrict__ dst,
                               const float* __restrict__ att3, int e) {
    int ee = blockIdx.x * 8 + (threadIdx.x >> 4);
    int c = threadIdx.x & 15;
    bool ok = ee < e;
    int s = ok ? src[ee] : 0, d = ok ? dst[ee] : 0;
    float ev = ok ? leakyr(g_xl[(size_t)s * 16 + c] + g_xr[(size_t)d * 16 + c] + g_ea23[(size_t)ee * 48 + 32 + c]) : 0.f;
    float p = ev * att3[c];
    p += __shfl_xor_sync(0xFFFFFFFFu, p, 8);
    p += __shfl_xor_sync(0xFFFFFFFFu, p, 4);
    p += __shfl_xor_sync(0xFFFFFFFFu, p, 2);
    p += __shfl_xor_sync(0xFFFFFFFFu, p, 1);
    if (ok && c == 0) g_logits[ee] = p;
}

// ---------------- finish layer3 ------------------------------------------------
__global__ void k_node_fin3(const float* __restrict__ bias3, int n) {
    int i = blockIdx.x * blockDim.x + threadIdx.x;
    if (i >= n * 16) return;
    g_x3[i] = g_num3[i] / (g_s3[i >> 4] + 1e-16f) + bias3[i & 15];
}

// ---------------- P/Q precompute: P = x3 @ W1[0:16], Q = x3 @ W1[16:32] ------
// 16 nodes/block, 256 threads. P -> g_xl[node*64+j], Q -> g_xr[node*64+j].
__global__ void __launch_bounds__(256) k_pq(const float* __restrict__ W1, int n) {
    __shared__ float w1s[32 * 64];
    __shared__ float x3s[16][17];
    int tid = threadIdx.x;
    int nb = blockIdx.x * 16;
    for (int i = tid; i < 512; i += 256)
        reinterpret_cast<float4*>(w1s)[i] = reinterpret_cast<const float4*>(W1)[i];
    {
        int node = tid >> 4, k = tid & 15;
        x3s[node][k] = (nb + node < n) ? g_x3[(size_t)(nb + node) * 16 + k] : 0.f;
    }
    __syncthreads();
#pragma unroll
    for (int i = 0; i < 8; i++) {
        int o = i * 256 + tid;
        int node = o >> 7, col = o & 127;
        int hh = col >> 6, j = col & 63;
        float acc = 0.f;
#pragma unroll
        for (int k = 0; k < 16; k++) acc += x3s[node][k] * w1s[(hh * 16 + k) * 64 + j];
        if (nb + node < n) {
            if (hh == 0) g_xl[(size_t)(nb + node) * 64 + j] = acc;
            else         g_xr[(size_t)(nb + node) * 64 + j] = acc;
        }
    }
}

// ---------------- edge MLP: 32 edges/block using P/Q ---------------------------
__global__ void __launch_bounds__(256) k_mlp(
        const int* __restrict__ src, const int* __restrict__ dst,
        const float* __restrict__ b1, const float* __restrict__ W2,
        const float* __restrict__ b2, const float* __restrict__ W3,
        const float* __restrict__ b3, float* __restrict__ out, int e) {
    __shared__ float w2s[64 * 32];
    __shared__ float h1s[32][68];
    __shared__ float h2s[32][33];
    __shared__ int   se[32], de[32];
    __shared__ float w3s[32];
    int tid = threadIdx.x;
    int eb = blockIdx.x * 32;

    for (int i = tid; i < 512; i += 256)
        reinterpret_cast<float4*>(w2s)[i] = reinterpret_cast<const float4*>(W2)[i];
    if (tid < 32) {
        int ee = eb + tid;
        se[tid] = (ee < e) ? src[ee] : 0;
        de[tid] = (ee < e) ? dst[ee] : 0;
        w3s[tid] = W3[tid];
    }
    __syncthreads();

    // stage1: h1 = relu(P[src] + Q[dst] + b1)
#pragma unroll
    for (int i = 0; i < 8; i++) {
        int o = i * 256 + tid;
        int le = o >> 6, j = o & 63;
        float v = g_xl[(size_t)se[le] * 64 + j] + g_xr[(size_t)de[le] * 64 + j] + b1[j];
        h1s[le][j] = fmaxf(v, 0.f);
    }
    __syncthreads();

    // stage2: h2 = relu(h1 @ W2 + b2). 128 threads: (j 0..31) x (eg 0..3 of 8 edges)
    if (tid < 128) {
        int j = tid & 31, eg = tid >> 5;
        float acc[8];
#pragma unroll
        for (int r = 0; r < 8; r++) acc[r] = b2[j];
#pragma unroll
        for (int k4 = 0; k4 < 16; k4++) {
            int k = k4 * 4;
            float w0 = w2s[(k + 0) * 32 + j];
            float w1 = w2s[(k + 1) * 32 + j];
            float w2v = w2s[(k + 2) * 32 + j];
            float w3v = w2s[(k + 3) * 32 + j];
#pragma unroll
            for (int r = 0; r < 8; r++) {
                float4 hv = *reinterpret_cast<const float4*>(&h1s[eg * 8 + r][k]);
                acc[r] += hv.x * w0 + hv.y * w1 + hv.z * w2v + hv.w * w3v;
            }
        }
#pragma unroll
        for (int r = 0; r < 8; r++) h2s[eg * 8 + r][j] = fmaxf(acc[r], 0.f);
    }
    __syncthreads();

    // stage3: out = h2 @ W3 + b3. warp 0, lane = edge
    if (tid < 32) {
        float p = 0.f;
#pragma unroll
        for (int k = 0; k < 32; k++) p += h2s[tid][k] * w3s[k];
        int ee = eb + tid;
        if (ee < e) out[ee] = p + b3[0];
    }
}

// ---------------- launch --------------------------------------------------------
extern "C" void kernel_launch(void* const* d_in, const int* in_sizes, int n_in,
                              void* d_out, int out_size) {
    const int*   node_ids = (const int*)  d_in[0];
    const int*   eidx     = (const int*)  d_in[1];
    const float* eattr    = (const float*)d_in[2];
    const float* emb      = (const float*)d_in[3];
    const float* l1_Wl   = (const float*)d_in[4];
    const float* l1_bl   = (const float*)d_in[5];
    const float* l1_Wr   = (const float*)d_in[6];
    const float* l1_br   = (const float*)d_in[7];
    const float* l1_We   = (const float*)d_in[8];
    const float* l1_att  = (const float*)d_in[9];
    const float* l1_bias = (const float*)d_in[10];
    const float* l2_Wl   = (const float*)d_in[11];
    const float* l2_bl   = (const float*)d_in[12];
    const float* l2_Wr   = (const float*)d_in[13];
    const float* l2_br   = (const float*)d_in[14];
    const float* l2_We   = (const float*)d_in[15];
    const float* l2_att  = (const float*)d_in[16];
    const float* l2_bias = (const float*)d_in[17];
    const float* l3_Wl   = (const float*)d_in[18];
    const float* l3_bl   = (const float*)d_in[19];
    const float* l3_Wr   = (const float*)d_in[20];
    const float* l3_br   = (const float*)d_in[21];
    const float* l3_We   = (const float*)d_in[22];
    const float* l3_att  = (const float*)d_in[23];
    const float* l3_bias = (const float*)d_in[24];
    const float* mlp_W1  = (const float*)d_in[25];
    const float* mlp_b1  = (const float*)d_in[26];
    const float* mlp_W2  = (const float*)d_in[27];
    const float* mlp_b2  = (const float*)d_in[28];
    const float* mlp_W3  = (const float*)d_in[29];
    const float* mlp_b3  = (const float*)d_in[30];

    int n = in_sizes[0];
    int e = in_sizes[1] / 2;
    const int* src = eidx;
    const int* dst = eidx + e;
    float* out = (float*)d_out;

    static bool attr_set = false;
    if (!attr_set) {
        cudaFuncSetAttribute(k_edge_mma, cudaFuncAttributeMaxDynamicSharedMemorySize, SM_EP_TOTAL);
        attr_set = true;
    }

    // ---- prep + layer 1 (edge GEMM is launch #4 for ncu visibility) ----
    k_prep_w<<<(NCOL * KPAD + 255) / 256, 256>>>(l1_We, l2_We, l3_We);
    k_node1<<<n, 64>>>(node_ids, emb, l1_Wl, l1_bl, l1_Wr, l1_br, n);
    k_init1<<<(n * 64 + 255) / 256, 256>>>(n);
    k_edge_mma<<<(e + 127) / 128, 128, SM_EP_TOTAL>>>(eattr, src, dst, l1_att, e);
    k_soft1<<<(e * 16 + 255) / 256, 256>>>(src, dst, e);
    k_node_fin1<<<(n + 15) / 16, 256>>>(l1_bias, l2_Wl, l2_bl, l2_Wr, l2_br, n);

    // ---- layer 2 ----
    k_edge_logits2<<<(e + 7) / 8, 256>>>(src, dst, l2_att, e);
    k_soft2<<<(e * 8 + 255) / 256, 256>>>(src, dst, e);
    k_node_fin2<<<(n + 15) / 16, 256>>>(l2_bias, l3_Wl, l3_bl, l3_Wr, l3_br, n);

    // ---- layer 3 ----
    k_edge_logits3<<<(e + 7) / 8, 128>>>(src, dst, l3_att, e);
    k_soft3<<<(e * 4 + 255) / 256, 256>>>(src, dst, e);
    k_node_fin3<<<(n * 16 + 255) / 256, 256>>>(l3_bias, n);

    // ---- edge MLP via P/Q ----
    k_pq<<<(n + 15) / 16, 256>>>(mlp_W1, n);
    k_mlp<<<(e + 31) / 32, 256>>>(src, dst, mlp_b1, mlp_W2, mlp_b2,
                                  mlp_W3, mlp_b3, out, e);
}

// round 10
// speedup vs baseline: 1.2233x; 1.0348x over previous
#include <cuda_runtime.h>
#include <cuda_bf16.h>
#include <math.h>
#include <stdint.h>

#define N_CAP 50048
#define E_CAP 500224
#define KPAD 416
#define NCOL 112

// ---------------- scratch ----------------------------------------------------
__device__ float g_xl[N_CAP * 64];
__device__ float g_xr[N_CAP * 64];
__device__ float g_s1[N_CAP * 4];
__device__ float g_num1[N_CAP * 64];
__device__ float g_s2[N_CAP * 2];
__device__ float g_num2[N_CAP * 32];
__device__ float g_s3[N_CAP];
__device__ float g_num3[N_CAP * 16];
__device__ float g_ea23[E_CAP * 48];
__device__ float g_x3[N_CAP * 16];
__device__ __nv_bfloat16 g_Bh[NCOL * KPAD];
__device__ __nv_bfloat16 g_Bl[NCOL * KPAD];

// ---------------- helpers ----------------------------------------------------
__device__ __forceinline__ float leakyr(float v) { return v > 0.f ? v : 0.2f * v; }
__device__ __forceinline__ float eluf(float v)   { return v > 0.f ? v : (expf(v) - 1.f); }

__device__ __forceinline__ void red2(float* p, float a, float b) {
    asm volatile("red.global.add.v2.f32 [%0], {%1, %2};"
                 :: "l"(p), "f"(a), "f"(b) : "memory");
}
__device__ __forceinline__ void red1(float* p, float a) {
    asm volatile("red.global.add.f32 [%0], %1;" :: "l"(p), "f"(a) : "memory");
}
__device__ __forceinline__ uint32_t smem_u32(const void* p) {
    uint32_t a;
    asm("{ .reg .u64 t; cvta.to.shared.u64 t, %1; cvt.u32.u64 %0, t; }" : "=r"(a) : "l"(p));
    return a;
}
__device__ __forceinline__ void mma_bf16(float* d, uint32_t a0, uint32_t a1,
                                         uint32_t a2, uint32_t a3,
                                         uint32_t b0, uint32_t b1) {
    asm volatile(
        "mma.sync.aligned.m16n8k16.row.col.f32.bf16.bf16.f32 "
        "{%0,%1,%2,%3}, {%4,%5,%6,%7}, {%8,%9}, {%0,%1,%2,%3};"
        : "+f"(d[0]), "+f"(d[1]), "+f"(d[2]), "+f"(d[3])
        : "r"(a0), "r"(a1), "r"(a2), "r"(a3), "r"(b0), "r"(b1));
}
__device__ __forceinline__ void cp16(uint32_t dst_smem, const void* src) {
    asm volatile("cp.async.cg.shared.global [%0], [%1], 16;"
                 :: "r"(dst_smem), "l"(src) : "memory");
}
#define CP_COMMIT()  asm volatile("cp.async.commit_group;" ::: "memory")
#define CP_WAIT(n)   asm volatile("cp.async.wait_group %0;" :: "n"(n) : "memory")

__device__ __forceinline__ void cvtHL(float x0, float x1, uint32_t& h, uint32_t& l) {
    __nv_bfloat16 h0 = __float2bfloat16(x0);
    __nv_bfloat16 h1 = __float2bfloat16(x1);
    __nv_bfloat162 hb(h0, h1);
    h = *reinterpret_cast<uint32_t*>(&hb);
    __nv_bfloat162 lb(__float2bfloat16(x0 - __bfloat162float(h0)),
                      __float2bfloat16(x1 - __bfloat162float(h1)));
    l = *reinterpret_cast<uint32_t*>(&lb);
}

// ---------------- weight prep: combined, padded, bf16 hi/lo, [n][k] ----------
__global__ void k_prep_w(const float* __restrict__ We1, const float* __restrict__ We2,
                         const float* __restrict__ We3) {
    int idx = blockIdx.x * blockDim.x + threadIdx.x;
    if (idx >= NCOL * KPAD) return;
    int j = idx / KPAD, k = idx - j * KPAD;
    float w = 0.f;
    if (k < 385) {
        if (j < 64)      w = We1[k * 64 + j];
        else if (j < 96) w = We2[k * 32 + (j - 64)];
        else             w = We3[k * 16 + (j - 96)];
    }
    __nv_bfloat16 h = __float2bfloat16(w);
    __nv_bfloat16 l = __float2bfloat16(w - __bfloat162float(h));
    g_Bh[idx] = h;
    g_Bl[idx] = l;
}

// ---------------- layer 1 node projection -----------------------------------
__global__ void k_node1(const int* __restrict__ node_ids,
                        const float* __restrict__ emb,
                        const float* __restrict__ Wl, const float* __restrict__ bl,
                        const float* __restrict__ Wr, const float* __restrict__ br,
                        int n) {
    int node = blockIdx.x;
    if (node >= n) return;
    int c = threadIdx.x;  // 0..63
    __shared__ float sx[32];
    if (c < 32) sx[c] = emb[node_ids[node] * 32 + c];
    __syncthreads();
    float al = bl[c], ar = br[c];
#pragma unroll
    for (int k = 0; k < 32; k++) {
        float xv = sx[k];
        al += xv * Wl[k * 64 + c];
        ar += xv * Wr[k * 64 + c];
    }
    g_xl[node * 64 + c] = al;
    g_xr[node * 64 + c] = ar;
}

__global__ void k_init1(int n) {
    int i = blockIdx.x * blockDim.x + threadIdx.x;
    if (i < n * 64) g_num1[i] = 0.f;
    if (i < n * 4) g_s1[i] = 0.f;
}

// ---------------- bf16 mma.sync edge projection + FUSED layer-1 softmax ------
#define SA_STRIDE 36
#define SB_STRIDE 40
#define SM_AH 0
#define SM_AL (128 * SA_STRIDE * 2)
#define SM_BH (SM_AL + 128 * SA_STRIDE * 2)
#define SM_BL (SM_BH + 2 * 112 * SB_STRIDE * 2)
#define SM_EP_TOTAL (SM_BL + 2 * 112 * SB_STRIDE * 2)

__global__ void __launch_bounds__(128, 2) k_edge_mma(
        const float* __restrict__ eattr,
        const int* __restrict__ src, const int* __restrict__ dst,
        const float* __restrict__ att1, int e) {
    extern __shared__ char smem[];
    __nv_bfloat16* sAh = reinterpret_cast<__nv_bfloat16*>(smem + SM_AH);
    __nv_bfloat16* sAl = reinterpret_cast<__nv_bfloat16*>(smem + SM_AL);
    const uint32_t sBh_u = smem_u32(smem + SM_BH);
    const uint32_t sBl_u = smem_u32(smem + SM_BL);

    const int tid  = threadIdx.x;
    const int w    = tid >> 5;
    const int lane = tid & 31;
    const int g    = lane >> 2;
    const int c    = lane & 3;
    const int eb   = blockIdx.x * 128;
    const int nE   = min(128, e - eb);

    float D[2][14][4];
#pragma unroll
    for (int tt = 0; tt < 2; tt++)
#pragma unroll
        for (int nt = 0; nt < 14; nt++)
#pragma unroll
            for (int q = 0; q < 4; q++) D[tt][nt][q] = 0.f;

    float aR[32];

#define LOAD_A(kc_)                                                          \
    {                                                                        \
        int k0 = (kc_) * 32;                                                 \
        _Pragma("unroll")                                                    \
        for (int it = 0; it < 16; it++) {                                    \
            int p = it * 128 + tid;                                          \
            int row = p >> 4, cp = p & 15;                                   \
            int col = k0 + cp * 2;                                           \
            float v0 = 0.f, v1 = 0.f;                                        \
            if (row < nE) {                                                  \
                const float* rp = eattr + (size_t)(eb + row) * 385;          \
                if (col < 385)     v0 = rp[col];                             \
                if (col + 1 < 385) v1 = rp[col + 1];                         \
            }                                                                \
            aR[2 * it] = v0; aR[2 * it + 1] = v1;                            \
        }                                                                    \
    }

#define STORE_A()                                                            \
    {                                                                        \
        _Pragma("unroll")                                                    \
        for (int it = 0; it < 16; it++) {                                    \
            int p = it * 128 + tid;                                          \
            int row = p >> 4, cp = p & 15;                                   \
            float v0 = aR[2 * it], v1 = aR[2 * it + 1];                      \
            __nv_bfloat16 h0 = __float2bfloat16(v0);                         \
            __nv_bfloat16 h1 = __float2bfloat16(v1);                         \
            __nv_bfloat16 l0 = __float2bfloat16(v0 - __bfloat162float(h0));  \
            __nv_bfloat16 l1 = __float2bfloat16(v1 - __bfloat162float(h1));  \
            int o = row * SA_STRIDE + cp * 2;                                \
            *reinterpret_cast<__nv_bfloat162*>(sAh + o) = __nv_bfloat162(h0, h1); \
            *reinterpret_cast<__nv_bfloat162*>(sAl + o) = __nv_bfloat162(l0, l1); \
        }                                                                    \
    }

#define CA_B(kc_, buf_)                                                      \
    {                                                                        \
        const char* bh = reinterpret_cast<const char*>(g_Bh);                \
        const char* bl = reinterpret_cast<const char*>(g_Bl);                \
        int koff = (kc_) * 64;                                               \
        uint32_t dsth = sBh_u + (buf_) * 112 * SB_STRIDE * 2;                \
        uint32_t dstl = sBl_u + (buf_) * 112 * SB_STRIDE * 2;                \
        for (int i = tid; i < 448; i += 128) {                               \
            int row = i >> 2, q = i & 3;                                     \
            cp16(dsth + row * (SB_STRIDE * 2) + q * 16,                      \
                 bh + (size_t)row * (KPAD * 2) + koff + q * 16);             \
            cp16(dstl + row * (SB_STRIDE * 2) + q * 16,                      \
                 bl + (size_t)row * (KPAD * 2) + koff + q * 16);             \
        }                                                                    \
    }

    LOAD_A(0);
    CA_B(0, 0);
    CP_COMMIT();

    for (int kc = 0; kc < 13; kc++) {
        __syncthreads();
        STORE_A();
        if (kc < 12) {
            LOAD_A(kc + 1);
            CA_B(kc + 1, (kc + 1) & 1);
            CP_COMMIT();
            CP_WAIT(1);
        } else {
            CP_WAIT(0);
        }
        __syncthreads();

        const __nv_bfloat16* bhp = reinterpret_cast<const __nv_bfloat16*>(smem + SM_BH)
                                   + (kc & 1) * 112 * SB_STRIDE;
        const __nv_bfloat16* blp = reinterpret_cast<const __nv_bfloat16*>(smem + SM_BL)
                                   + (kc & 1) * 112 * SB_STRIDE;
#pragma unroll
        for (int k16 = 0; k16 < 2; k16++) {
            int kb = k16 * 16;
            uint32_t ah[2][4], al_[2][4];
#pragma unroll
            for (int tt = 0; tt < 2; tt++) {
                int m0 = w * 32 + tt * 16;
                int rA = (m0 + g) * SA_STRIDE, rB = (m0 + g + 8) * SA_STRIDE;
                int c0 = kb + 2 * c, c1 = kb + 2 * c + 8;
                ah[tt][0] = *reinterpret_cast<const uint32_t*>(sAh + rA + c0);
                ah[tt][1] = *reinterpret_cast<const uint32_t*>(sAh + rB + c0);
                ah[tt][2] = *reinterpret_cast<const uint32_t*>(sAh + rA + c1);
                ah[tt][3] = *reinterpret_cast<const uint32_t*>(sAh + rB + c1);
                al_[tt][0] = *reinterpret_cast<const uint32_t*>(sAl + rA + c0);
                al_[tt][1] = *reinterpret_cast<const uint32_t*>(sAl + rB + c0);
                al_[tt][2] = *reinterpret_cast<const uint32_t*>(sAl + rA + c1);
                al_[tt][3] = *reinterpret_cast<const uint32_t*>(sAl + rB + c1);
            }
#pragma unroll
            for (int nt = 0; nt < 14; nt++) {
                int n = nt * 8 + g;
                int c0 = kb + 2 * c, c1 = kb + 2 * c + 8;
                uint32_t bh0 = *reinterpret_cast<const uint32_t*>(bhp + n * SB_STRIDE + c0);
                uint32_t bh1 = *reinterpret_cast<const uint32_t*>(bhp + n * SB_STRIDE + c1);
                uint32_t bl0 = *reinterpret_cast<const uint32_t*>(blp + n * SB_STRIDE + c0);
                uint32_t bl1 = *reinterpret_cast<const uint32_t*>(blp + n * SB_STRIDE + c1);
#pragma unroll
                for (int tt = 0; tt < 2; tt++) {
                    mma_bf16(D[tt][nt], ah[tt][0], ah[tt][1], ah[tt][2], ah[tt][3], bh0, bh1);
                    mma_bf16(D[tt][nt], al_[tt][0], al_[tt][1], al_[tt][2], al_[tt][3], bh0, bh1);
                    mma_bf16(D[tt][nt], ah[tt][0], ah[tt][1], ah[tt][2], ah[tt][3], bl0, bl1);
                }
            }
        }
    }

    // -------- epilogue: logits1 -> exp -> fused num1/s1 reduction + ea23 -----
#pragma unroll
    for (int tt = 0; tt < 2; tt++) {
        int m0 = w * 32 + tt * 16;
        int rA = m0 + g, rB = m0 + g + 8;
        int eeA = eb + rA, eeB = eb + rB;
        bool vA = rA < nE, vB = rB < nE;
        int sA_ = vA ? src[eeA] : 0, dA_ = vA ? dst[eeA] : 0;
        int sB_ = vB ? src[eeB] : 0, dB_ = vB ? dst[eeB] : 0;

        float exA[4], exB[4];
#pragma unroll
        for (int h = 0; h < 4; h++) {
            float pA = 0.f, pB = 0.f;
#pragma unroll
            for (int q = 0; q < 2; q++) {
                int nt = 2 * h + q;
                int col = nt * 8 + c * 2;
                float at0 = att1[col], at1 = att1[col + 1];
                float2 xjA = *reinterpret_cast<const float2*>(g_xl + (size_t)sA_ * 64 + col);
                float2 xiA = *reinterpret_cast<const float2*>(g_xr + (size_t)dA_ * 64 + col);
                pA += leakyr(D[tt][nt][0] + xjA.x + xiA.x) * at0
                    + leakyr(D[tt][nt][1] + xjA.y + xiA.y) * at1;
                float2 xjB = *reinterpret_cast<const float2*>(g_xl + (size_t)sB_ * 64 + col);
                float2 xiB = *reinterpret_cast<const float2*>(g_xr + (size_t)dB_ * 64 + col);
                pB += leakyr(D[tt][nt][2] + xjB.x + xiB.x) * at0
                    + leakyr(D[tt][nt][3] + xjB.y + xiB.y) * at1;
            }
            pA += __shfl_xor_sync(0xFFFFFFFFu, pA, 1);
            pA += __shfl_xor_sync(0xFFFFFFFFu, pA, 2);
            pB += __shfl_xor_sync(0xFFFFFFFFu, pB, 1);
            pB += __shfl_xor_sync(0xFFFFFFFFu, pB, 2);
            exA[h] = expf(pA);
            exB[h] = expf(pB);
            if (c == 0) {
                if (vA) red1(&g_s1[(size_t)dA_ * 4 + h], exA[h]);
                if (vB) red1(&g_s1[(size_t)dB_ * 4 + h], exB[h]);
            }
        }
        // fused num1 accumulation: num1[d*64+col] += ex_h * xl[s*64+col]
#pragma unroll
        for (int nt = 0; nt < 8; nt++) {
            int col = nt * 8 + c * 2;
            int h = nt >> 1;
            if (vA) {
                float2 xj = *reinterpret_cast<const float2*>(g_xl + (size_t)sA_ * 64 + col);
                red2(g_num1 + (size_t)dA_ * 64 + col, exA[h] * xj.x, exA[h] * xj.y);
            }
            if (vB) {
                float2 xj = *reinterpret_cast<const float2*>(g_xl + (size_t)sB_ * 64 + col);
                red2(g_num1 + (size_t)dB_ * 64 + col, exB[h] * xj.x, exB[h] * xj.y);
            }
        }
        // ea23 stores
#pragma unroll
        for (int nt = 8; nt < 14; nt++) {
            int off = (nt < 12) ? (nt - 8) * 8 + c * 2
                                : 32 + (nt - 12) * 8 + c * 2;
            if (vA) *reinterpret_cast<float2*>(g_ea23 + (size_t)eeA * 48 + off) =
                        make_float2(D[tt][nt][0], D[tt][nt][1]);
            if (vB) *reinterpret_cast<float2*>(g_ea23 + (size_t)eeB * 48 + off) =
                        make_float2(D[tt][nt][2], D[tt][nt][3]);
        }
    }
}

// ---------------- finish layer1 + project layer2 (16 nodes/block) ------------
__global__ void __launch_bounds__(256) k_node_fin1(
        const float* __restrict__ bias1,
        const float* __restrict__ Wl2, const float* __restrict__ bl2,
        const float* __restrict__ Wr2, const float* __restrict__ br2, int n) {
    __shared__ float sx[16][65];
    int tid = threadIdx.x;
    int nb = blockIdx.x * 16;
#pragma unroll
    for (int i = 0; i < 4; i++) {
        int o = i * 256 + tid;
        int ln = o >> 6, cc = o & 63;
        int node = nb + ln;
        float v = 0.f;
        if (node < n)
            v = g_num1[(size_t)node * 64 + cc] / (g_s1[(size_t)node * 4 + (cc >> 4)] + 1e-16f) + bias1[cc];
        sx[ln][cc] = eluf(v);
    }
    __syncthreads();
    int c = tid & 63, ng = tid >> 6;
    const float* W  = (c < 32) ? Wl2 : Wr2;
    const float* bb = (c < 32) ? bl2 : br2;
    int c2 = c & 31;
    float a[4];
#pragma unroll
    for (int r = 0; r < 4; r++) a[r] = bb[c2];
    for (int k = 0; k < 64; k++) {
        float wv = W[k * 32 + c2];
#pragma unroll
        for (int r = 0; r < 4; r++) a[r] += sx[ng * 4 + r][k] * wv;
    }
#pragma unroll
    for (int r = 0; r < 4; r++) {
        int node = nb + ng * 4 + r;
        if (node < n) {
            if (c < 32) { g_xl[(size_t)node * 32 + c2] = a[r]; g_num2[(size_t)node * 32 + c2] = 0.f; }
            else          g_xr[(size_t)node * 32 + c2] = a[r];
        }
    }
    if (tid < 32) {
        int node = nb + (tid >> 1);
        if (node < n) g_s2[(size_t)node * 2 + (tid & 1)] = 0.f;
    }
}

// ---------------- layer-2 logits + FUSED softmax accumulation -----------------
__global__ void k_l2(const int* __restrict__ src, const int* __restrict__ dst,
                     const float* __restrict__ att2, int e) {
    int ee = blockIdx.x * 8 + (threadIdx.x >> 5);
    if (ee >= e) return;
    int c = threadIdx.x & 31;
    int s = src[ee], d = dst[ee];
    float xj = g_xl[(size_t)s * 32 + c];
    float ev = leakyr(xj + g_xr[(size_t)d * 32 + c] + g_ea23[(size_t)ee * 48 + c]);
    float p = ev * att2[c];
    p += __shfl_xor_sync(0xFFFFFFFFu, p, 8);
    p += __shfl_xor_sync(0xFFFFFFFFu, p, 4);
    p += __shfl_xor_sync(0xFFFFFFFFu, p, 2);
    p += __shfl_xor_sync(0xFFFFFFFFu, p, 1);
    float ex = expf(p);
    if ((c & 15) == 0) red1(&g_s2[(size_t)d * 2 + (c >> 4)], ex);
    red1(&g_num2[(size_t)d * 32 + c], ex * xj);
}

// ---------------- finish layer2 + project layer3 (16 nodes/block) ------------
__global__ void __launch_bounds__(256) k_node_fin2(
        const float* __restrict__ bias2,
        const float* __restrict__ Wl3, const float* __restrict__ bl3,
        const float* __restrict__ Wr3, const float* __restrict__ br3, int n) {
    __shared__ float sx[16][33];
    int tid = threadIdx.x;
    int nb = blockIdx.x * 16;
#pragma unroll
    for (int i = 0; i < 2; i++) {
        int o = i * 256 + tid;
        int ln = o >> 5, cc = o & 31;
        int node = nb + ln;
        float v = 0.f;
        if (node < n)
            v = g_num2[(size_t)node * 32 + cc] / (g_s2[(size_t)node * 2 + (cc >> 4)] + 1e-16f) + bias2[cc];
        sx[ln][cc] = eluf(v);
    }
    __syncthreads();
    int c = tid & 31, ng = tid >> 5;
    const float* W  = (c < 16) ? Wl3 : Wr3;
    const float* bb = (c < 16) ? bl3 : br3;
    int c2 = c & 15;
    float a[2];
    a[0] = bb[c2]; a[1] = bb[c2];
    for (int k = 0; k < 32; k++) {
        float wv = W[k * 16 + c2];
        a[0] += sx[ng * 2 + 0][k] * wv;
        a[1] += sx[ng * 2 + 1][k] * wv;
    }
#pragma unroll
    for (int r = 0; r < 2; r++) {
        int node = nb + ng * 2 + r;
        if (node < n) {
            if (c < 16) { g_xl[(size_t)node * 16 + c2] = a[r]; g_num3[(size_t)node * 16 + c2] = 0.f; }
            else          g_xr[(size_t)node * 16 + c2] = a[r];
        }
    }
    if (tid < 16) {
        int node = nb + tid;
        if (node < n) g_s3[node] = 0.f;
    }
}

// ---------------- layer-3 logits + FUSED softmax accumulation -----------------
__global__ void k_l3(const int* __restrict__ src, const int* __restrict__ dst,
                     const float* __restrict__ att3, int e) {
    int ee = blockIdx.x * 8 + (threadIdx.x >> 4);
    int c = threadIdx.x & 15;
    bool ok = ee < e;
    int s = ok ? src[ee] : 0, d = ok ? dst[ee] : 0;
    float xj = ok ? g_xl[(size_t)s * 16 + c] : 0.f;
    float ev = ok ? leakyr(xj + g_xr[(size_t)d * 16 + c] + g_ea23[(size_t)ee * 48 + 32 + c]) : 0.f;
    float p = ev * att3[c];
    p += __shfl_xor_sync(0xFFFFFFFFu, p, 8);
    p += __shfl_xor_sync(0xFFFFFFFFu, p, 4);
    p += __shfl_xor_sync(0xFFFFFFFFu, p, 2);
    p += __shfl_xor_sync(0xFFFFFFFFu, p, 1);
    if (ok) {
        float ex = expf(p);
        if (c == 0) red1(&g_s3[d], ex);
        red1(&g_num3[(size_t)d * 16 + c], ex * xj);
    }
}

// ---------------- finish layer3 ------------------------------------------------
__global__ void k_node_fin3(const float* __restrict__ bias3, int n) {
    int i = blockIdx.x * blockDim.x + threadIdx.x;
    if (i >= n * 16) return;
    g_x3[i] = g_num3[i] / (g_s3[i >> 4] + 1e-16f) + bias3[i & 15];
}

// ---------------- P/Q precompute -----------------------------------------------
__global__ void __launch_bounds__(256) k_pq(const float* __restrict__ W1, int n) {
    __shared__ float w1s[32 * 64];
    __shared__ float x3s[16][17];
    int tid = threadIdx.x;
    int nb = blockIdx.x * 16;
    for (int i = tid; i < 512; i += 256)
        reinterpret_cast<float4*>(w1s)[i] = reinterpret_cast<const float4*>(W1)[i];
    {
        int node = tid >> 4, k = tid & 15;
        x3s[node][k] = (nb + node < n) ? g_x3[(size_t)(nb + node) * 16 + k] : 0.f;
    }
    __syncthreads();
#pragma unroll
    for (int i = 0; i < 8; i++) {
        int o = i * 256 + tid;
        int node = o >> 7, col = o & 127;
        int hh = col >> 6, j = col & 63;
        float acc = 0.f;
#pragma unroll
        for (int k = 0; k < 16; k++) acc += x3s[node][k] * w1s[(hh * 16 + k) * 64 + j];
        if (nb + node < n) {
            if (hh == 0) g_xl[(size_t)(nb + node) * 64 + j] = acc;
            else         g_xr[(size_t)(nb + node) * 64 + j] = acc;
        }
    }
}

// ---------------- edge MLP: 32 edges/block using P/Q ---------------------------
__global__ void __launch_bounds__(256) k_mlp(
        const int* __restrict__ src, const int* __restrict__ dst,
        const float* __restrict__ b1, const float* __restrict__ W2,
        const float* __restrict__ b2, const float* __restrict__ W3,
        const float* __restrict__ b3, float* __restrict__ out, int e) {
    __shared__ float w2s[64 * 32];
    __shared__ float h1s[32][68];
    __shared__ float h2s[32][33];
    __shared__ int   se[32], de[32];
    __shared__ float w3s[32];
    int tid = threadIdx.x;
    int eb = blockIdx.x * 32;

    for (int i = tid; i < 512; i += 256)
        reinterpret_cast<float4*>(w2s)[i] = reinterpret_cast<const float4*>(W2)[i];
    if (tid < 32) {
        int ee = eb + tid;
        se[tid] = (ee < e) ? src[ee] : 0;
        de[tid] = (ee < e) ? dst[ee] : 0;
        w3s[tid] = W3[tid];
    }
    __syncthreads();

#pragma unroll
    for (int i = 0; i < 8; i++) {
        int o = i * 256 + tid;
        int le = o >> 6, j = o & 63;
        float v = g_xl[(size_t)se[le] * 64 + j] + g_xr[(size_t)de[le] * 64 + j] + b1[j];
        h1s[le][j] = fmaxf(v, 0.f);
    }
    __syncthreads();

    if (tid < 128) {
        int j = tid & 31, eg = tid >> 5;
        float acc[8];
#pragma unroll
        for (int r = 0; r < 8; r++) acc[r] = b2[j];
#pragma unroll
        for (int k4 = 0; k4 < 16; k4++) {
            int k = k4 * 4;
            float w0 = w2s[(k + 0) * 32 + j];
            float w1 = w2s[(k + 1) * 32 + j];
            float w2v = w2s[(k + 2) * 32 + j];
            float w3v = w2s[(k + 3) * 32 + j];
#pragma unroll
            for (int r = 0; r < 8; r++) {
                float4 hv = *reinterpret_cast<const float4*>(&h1s[eg * 8 + r][k]);
                acc[r] += hv.x * w0 + hv.y * w1 + hv.z * w2v + hv.w * w3v;
            }
        }
#pragma unroll
        for (int r = 0; r < 8; r++) h2s[eg * 8 + r][j] = fmaxf(acc[r], 0.f);
    }
    __syncthreads();

    if (tid < 32) {
        float p = 0.f;
#pragma unroll
        for (int k = 0; k < 32; k++) p += h2s[tid][k] * w3s[k];
        int ee = eb + tid;
        if (ee < e) out[ee] = p + b3[0];
    }
}

// ---------------- launch --------------------------------------------------------
extern "C" void kernel_launch(void* const* d_in, const int* in_sizes, int n_in,
                              void* d_out, int out_size) {
    const int*   node_ids = (const int*)  d_in[0];
    const int*   eidx     = (const int*)  d_in[1];
    const float* eattr    = (const float*)d_in[2];
    const float* emb      = (const float*)d_in[3];
    const float* l1_Wl   = (const float*)d_in[4];
    const float* l1_bl   = (const float*)d_in[5];
    const float* l1_Wr   = (const float*)d_in[6];
    const float* l1_br   = (const float*)d_in[7];
    const float* l1_We   = (const float*)d_in[8];
    const float* l1_att  = (const float*)d_in[9];
    const float* l1_bias = (const float*)d_in[10];
    const float* l2_Wl   = (const float*)d_in[11];
    const float* l2_bl   = (const float*)d_in[12];
    const float* l2_Wr   = (const float*)d_in[13];
    const float* l2_br   = (const float*)d_in[14];
    const float* l2_We   = (const float*)d_in[15];
    const float* l2_att  = (const float*)d_in[16];
    const float* l2_bias = (const float*)d_in[17];
    const float* l3_Wl   = (const float*)d_in[18];
    const float* l3_bl   = (const float*)d_in[19];
    const float* l3_Wr   = (const float*)d_in[20];
    const float* l3_br   = (const float*)d_in[21];
    const float* l3_We   = (const float*)d_in[22];
    const float* l3_att  = (const float*)d_in[23];
    const float* l3_bias = (const float*)d_in[24];
    const float* mlp_W1  = (const float*)d_in[25];
    const float* mlp_b1  = (const float*)d_in[26];
    const float* mlp_W2  = (const float*)d_in[27];
    const float* mlp_b2  = (const float*)d_in[28];
    const float* mlp_W3  = (const float*)d_in[29];
    const float* mlp_b3  = (const float*)d_in[30];

    int n = in_sizes[0];
    int e = in_sizes[1] / 2;
    const int* src = eidx;
    const int* dst = eidx + e;
    float* out = (float*)d_out;

    static bool attr_set = false;
    if (!attr_set) {
        cudaFuncSetAttribute(k_edge_mma, cudaFuncAttributeMaxDynamicSharedMemorySize, SM_EP_TOTAL);
        attr_set = true;
    }

    // ---- prep + layer 1 (edge GEMM is launch #4 for ncu visibility) ----
    k_prep_w<<<(NCOL * KPAD + 255) / 256, 256>>>(l1_We, l2_We, l3_We);
    k_node1<<<n, 64>>>(node_ids, emb, l1_Wl, l1_bl, l1_Wr, l1_br, n);
    k_init1<<<(n * 64 + 255) / 256, 256>>>(n);
    k_edge_mma<<<(e + 127) / 128, 128, SM_EP_TOTAL>>>(eattr, src, dst, l1_att, e);
    k_node_fin1<<<(n + 15) / 16, 256>>>(l1_bias, l2_Wl, l2_bl, l2_Wr, l2_br, n);

    // ---- layer 2 (logits+softmax fused) ----
    k_l2<<<(e + 7) / 8, 256>>>(src, dst, l2_att, e);
    k_node_fin2<<<(n + 15) / 16, 256>>>(l2_bias, l3_Wl, l3_bl, l3_Wr, l3_br, n);

    // ---- layer 3 (logits+softmax fused) ----
    k_l3<<<(e + 7) / 8, 128>>>(src, dst, l3_att, e);
    k_node_fin3<<<(n * 16 + 255) / 256, 256>>>(l3_bias, n);

    // ---- edge MLP via P/Q ----
    k_pq<<<(n + 15) / 16, 256>>>(mlp_W1, n);
    k_mlp<<<(e + 31) / 32, 256>>>(src, dst, mlp_b1, mlp_W2, mlp_b2,
                                  mlp_W3, mlp_b3, out, e);
}

// round 11
// speedup vs baseline: 1.3308x; 1.0879x over previous
#include <cuda_runtime.h>
#include <cuda_fp16.h>
#include <math.h>
#include <stdint.h>

#define N_CAP 50048
#define E_CAP 500224
#define KPAD 416
#define NCOL 112

// ---------------- scratch ----------------------------------------------------
__device__ float g_xl[N_CAP * 64];
__device__ float g_xr[N_CAP * 64];
__device__ float g_s1[N_CAP * 4];
__device__ float g_num1[N_CAP * 64];
__device__ float g_s2[N_CAP * 2];
__device__ float g_num2[N_CAP * 32];
__device__ float g_s3[N_CAP];
__device__ float g_num3[N_CAP * 16];
__device__ float g_ea23[E_CAP * 48];
__device__ float g_x3[N_CAP * 16];
__device__ __half g_Bh[NCOL * KPAD];   // [112][416] fp16 weights (single plane)

// ---------------- helpers ----------------------------------------------------
__device__ __forceinline__ float leakyr(float v) { return v > 0.f ? v : 0.2f * v; }
__device__ __forceinline__ float eluf(float v)   { return v > 0.f ? v : (expf(v) - 1.f); }

__device__ __forceinline__ void red2(float* p, float a, float b) {
    asm volatile("red.global.add.v2.f32 [%0], {%1, %2};"
                 :: "l"(p), "f"(a), "f"(b) : "memory");
}
__device__ __forceinline__ void red1(float* p, float a) {
    asm volatile("red.global.add.f32 [%0], %1;" :: "l"(p), "f"(a) : "memory");
}
__device__ __forceinline__ uint32_t smem_u32(const void* p) {
    uint32_t a;
    asm("{ .reg .u64 t; cvta.to.shared.u64 t, %1; cvt.u32.u64 %0, t; }" : "=r"(a) : "l"(p));
    return a;
}
__device__ __forceinline__ void mma_f16(float* d, uint32_t a0, uint32_t a1,
                                        uint32_t a2, uint32_t a3,
                                        uint32_t b0, uint32_t b1) {
    asm volatile(
        "mma.sync.aligned.m16n8k16.row.col.f32.f16.f16.f32 "
        "{%0,%1,%2,%3}, {%4,%5,%6,%7}, {%8,%9}, {%0,%1,%2,%3};"
        : "+f"(d[0]), "+f"(d[1]), "+f"(d[2]), "+f"(d[3])
        : "r"(a0), "r"(a1), "r"(a2), "r"(a3), "r"(b0), "r"(b1));
}
__device__ __forceinline__ void cp16(uint32_t dst_smem, const void* src) {
    asm volatile("cp.async.cg.shared.global [%0], [%1], 16;"
                 :: "r"(dst_smem), "l"(src) : "memory");
}
#define CP_COMMIT()  asm volatile("cp.async.commit_group;" ::: "memory")
#define CP_WAIT(n)   asm volatile("cp.async.wait_group %0;" :: "n"(n) : "memory")

// fp16 hi/lo split of a float pair -> packed half2 words
__device__ __forceinline__ void cvtHL16(float x0, float x1, uint32_t& h, uint32_t& l) {
    __half h0 = __float2half_rn(x0);
    __half h1 = __float2half_rn(x1);
    __half2 hb = __halves2half2(h0, h1);
    h = *reinterpret_cast<uint32_t*>(&hb);
    __half2 lb = __halves2half2(__float2half_rn(x0 - __half2float(h0)),
                                __float2half_rn(x1 - __half2float(h1)));
    l = *reinterpret_cast<uint32_t*>(&lb);
}

// ---------------- weight prep: combined, padded, fp16, [n][k] -----------------
__global__ void k_prep_w(const float* __restrict__ We1, const float* __restrict__ We2,
                         const float* __restrict__ We3) {
    int idx = blockIdx.x * blockDim.x + threadIdx.x;
    if (idx >= NCOL * KPAD) return;
    int j = idx / KPAD, k = idx - j * KPAD;
    float w = 0.f;
    if (k < 385) {
        if (j < 64)      w = We1[k * 64 + j];
        else if (j < 96) w = We2[k * 32 + (j - 64)];
        else             w = We3[k * 16 + (j - 96)];
    }
    g_Bh[idx] = __float2half_rn(w);
}

// ---------------- layer 1 node projection -----------------------------------
__global__ void k_node1(const int* __restrict__ node_ids,
                        const float* __restrict__ emb,
                        const float* __restrict__ Wl, const float* __restrict__ bl,
                        const float* __restrict__ Wr, const float* __restrict__ br,
                        int n) {
    int node = blockIdx.x;
    if (node >= n) return;
    int c = threadIdx.x;  // 0..63
    __shared__ float sx[32];
    if (c < 32) sx[c] = emb[node_ids[node] * 32 + c];
    __syncthreads();
    float al = bl[c], ar = br[c];
#pragma unroll
    for (int k = 0; k < 32; k++) {
        float xv = sx[k];
        al += xv * Wl[k * 64 + c];
        ar += xv * Wr[k * 64 + c];
    }
    g_xl[node * 64 + c] = al;
    g_xr[node * 64 + c] = ar;
}

__global__ void k_init1(int n) {
    int i = blockIdx.x * blockDim.x + threadIdx.x;
    if (i < n * 64) g_num1[i] = 0.f;
    if (i < n * 4) g_s1[i] = 0.f;
}

// ---------------- fp16 2-split mma.sync edge projection + fused softmax ------
#define SA_STRIDE 36
#define SB_STRIDE 40
#define SM_AH 0
#define SM_AL (128 * SA_STRIDE * 2)
#define SM_BH (SM_AL + 128 * SA_STRIDE * 2)            // 18432
#define SM_EP_TOTAL (SM_BH + 2 * 112 * SB_STRIDE * 2)  // 36352

__global__ void __launch_bounds__(128, 2) k_edge_mma(
        const float* __restrict__ eattr,
        const int* __restrict__ src, const int* __restrict__ dst,
        const float* __restrict__ att1, int e) {
    extern __shared__ char smem[];
    __half* sAh = reinterpret_cast<__half*>(smem + SM_AH);
    __half* sAl = reinterpret_cast<__half*>(smem + SM_AL);
    const uint32_t sBh_u = smem_u32(smem + SM_BH);

    const int tid  = threadIdx.x;
    const int w    = tid >> 5;
    const int lane = tid & 31;
    const int g    = lane >> 2;
    const int c    = lane & 3;
    const int eb   = blockIdx.x * 128;
    const int nE   = min(128, e - eb);

    float D[2][14][4];
#pragma unroll
    for (int tt = 0; tt < 2; tt++)
#pragma unroll
        for (int nt = 0; nt < 14; nt++)
#pragma unroll
            for (int q = 0; q < 4; q++) D[tt][nt][q] = 0.f;

    float aR[32];

#define LOAD_A(kc_)                                                          \
    {                                                                        \
        int k0 = (kc_) * 32;                                                 \
        _Pragma("unroll")                                                    \
        for (int it = 0; it < 16; it++) {                                    \
            int p = it * 128 + tid;                                          \
            int row = p >> 4, cp = p & 15;                                   \
            int col = k0 + cp * 2;                                           \
            float v0 = 0.f, v1 = 0.f;                                        \
            if (row < nE) {                                                  \
                const float* rp = eattr + (size_t)(eb + row) * 385;          \
                if (col < 385)     v0 = rp[col];                             \
                if (col + 1 < 385) v1 = rp[col + 1];                         \
            }                                                                \
            aR[2 * it] = v0; aR[2 * it + 1] = v1;                            \
        }                                                                    \
    }

#define STORE_A()                                                            \
    {                                                                        \
        _Pragma("unroll")                                                    \
        for (int it = 0; it < 16; it++) {                                    \
            int p = it * 128 + tid;                                          \
            int row = p >> 4, cp = p & 15;                                   \
            uint32_t hh, ll;                                                 \
            cvtHL16(aR[2 * it], aR[2 * it + 1], hh, ll);                     \
            int o = row * SA_STRIDE + cp * 2;                                \
            *reinterpret_cast<uint32_t*>(sAh + o) = hh;                      \
            *reinterpret_cast<uint32_t*>(sAl + o) = ll;                      \
        }                                                                    \
    }

#define CA_B(kc_, buf_)                                                      \
    {                                                                        \
        const char* bh = reinterpret_cast<const char*>(g_Bh);                \
        int koff = (kc_) * 64;                                               \
        uint32_t dsth = sBh_u + (buf_) * 112 * SB_STRIDE * 2;                \
        for (int i = tid; i < 448; i += 128) {                               \
            int row = i >> 2, q = i & 3;                                     \
            cp16(dsth + row * (SB_STRIDE * 2) + q * 16,                      \
                 bh + (size_t)row * (KPAD * 2) + koff + q * 16);             \
        }                                                                    \
    }

    LOAD_A(0);
    CA_B(0, 0);
    CP_COMMIT();

    for (int kc = 0; kc < 13; kc++) {
        __syncthreads();
        STORE_A();
        if (kc < 12) {
            LOAD_A(kc + 1);
            CA_B(kc + 1, (kc + 1) & 1);
            CP_COMMIT();
            CP_WAIT(1);
        } else {
            CP_WAIT(0);
        }
        __syncthreads();

        const __half* bhp = reinterpret_cast<const __half*>(smem + SM_BH)
                            + (kc & 1) * 112 * SB_STRIDE;
#pragma unroll
        for (int k16 = 0; k16 < 2; k16++) {
            int kb = k16 * 16;
            uint32_t ah[2][4], al_[2][4];
#pragma unroll
            for (int tt = 0; tt < 2; tt++) {
                int m0 = w * 32 + tt * 16;
                int rA = (m0 + g) * SA_STRIDE, rB = (m0 + g + 8) * SA_STRIDE;
                int c0 = kb + 2 * c, c1 = kb + 2 * c + 8;
                ah[tt][0] = *reinterpret_cast<const uint32_t*>(sAh + rA + c0);
                ah[tt][1] = *reinterpret_cast<const uint32_t*>(sAh + rB + c0);
                ah[tt][2] = *reinterpret_cast<const uint32_t*>(sAh + rA + c1);
                ah[tt][3] = *reinterpret_cast<const uint32_t*>(sAh + rB + c1);
                al_[tt][0] = *reinterpret_cast<const uint32_t*>(sAl + rA + c0);
                al_[tt][1] = *reinterpret_cast<const uint32_t*>(sAl + rB + c0);
                al_[tt][2] = *reinterpret_cast<const uint32_t*>(sAl + rA + c1);
                al_[tt][3] = *reinterpret_cast<const uint32_t*>(sAl + rB + c1);
            }
#pragma unroll
            for (int nt = 0; nt < 14; nt++) {
                int n = nt * 8 + g;
                int c0 = kb + 2 * c, c1 = kb + 2 * c + 8;
                uint32_t bh0 = *reinterpret_cast<const uint32_t*>(bhp + n * SB_STRIDE + c0);
                uint32_t bh1 = *reinterpret_cast<const uint32_t*>(bhp + n * SB_STRIDE + c1);
#pragma unroll
                for (int tt = 0; tt < 2; tt++) {
                    mma_f16(D[tt][nt], ah[tt][0], ah[tt][1], ah[tt][2], ah[tt][3], bh0, bh1);
                    mma_f16(D[tt][nt], al_[tt][0], al_[tt][1], al_[tt][2], al_[tt][3], bh0, bh1);
                }
            }
        }
    }

    // -------- epilogue: logits1 -> exp -> fused num1/s1 reduction + ea23 -----
#pragma unroll
    for (int tt = 0; tt < 2; tt++) {
        int m0 = w * 32 + tt * 16;
        int rA = m0 + g, rB = m0 + g + 8;
        int eeA = eb + rA, eeB = eb + rB;
        bool vA = rA < nE, vB = rB < nE;
        int sA_ = vA ? src[eeA] : 0, dA_ = vA ? dst[eeA] : 0;
        int sB_ = vB ? src[eeB] : 0, dB_ = vB ? dst[eeB] : 0;

        float exA[4], exB[4];
#pragma unroll
        for (int h = 0; h < 4; h++) {
            float pA = 0.f, pB = 0.f;
#pragma unroll
            for (int q = 0; q < 2; q++) {
                int nt = 2 * h + q;
                int col = nt * 8 + c * 2;
                float at0 = att1[col], at1 = att1[col + 1];
                float2 xjA = *reinterpret_cast<const float2*>(g_xl + (size_t)sA_ * 64 + col);
                float2 xiA = *reinterpret_cast<const float2*>(g_xr + (size_t)dA_ * 64 + col);
                pA += leakyr(D[tt][nt][0] + xjA.x + xiA.x) * at0
                    + leakyr(D[tt][nt][1] + xjA.y + xiA.y) * at1;
                float2 xjB = *reinterpret_cast<const float2*>(g_xl + (size_t)sB_ * 64 + col);
                float2 xiB = *reinterpret_cast<const float2*>(g_xr + (size_t)dB_ * 64 + col);
                pB += leakyr(D[tt][nt][2] + xjB.x + xiB.x) * at0
                    + leakyr(D[tt][nt][3] + xjB.y + xiB.y) * at1;
            }
            pA += __shfl_xor_sync(0xFFFFFFFFu, pA, 1);
            pA += __shfl_xor_sync(0xFFFFFFFFu, pA, 2);
            pB += __shfl_xor_sync(0xFFFFFFFFu, pB, 1);
            pB += __shfl_xor_sync(0xFFFFFFFFu, pB, 2);
            exA[h] = expf(pA);
            exB[h] = expf(pB);
            if (c == 0) {
                if (vA) red1(&g_s1[(size_t)dA_ * 4 + h], exA[h]);
                if (vB) red1(&g_s1[(size_t)dB_ * 4 + h], exB[h]);
            }
        }
#pragma unroll
        for (int nt = 0; nt < 8; nt++) {
            int col = nt * 8 + c * 2;
            int h = nt >> 1;
            if (vA) {
                float2 xj = *reinterpret_cast<const float2*>(g_xl + (size_t)sA_ * 64 + col);
                red2(g_num1 + (size_t)dA_ * 64 + col, exA[h] * xj.x, exA[h] * xj.y);
            }
            if (vB) {
                float2 xj = *reinterpret_cast<const float2*>(g_xl + (size_t)sB_ * 64 + col);
                red2(g_num1 + (size_t)dB_ * 64 + col, exB[h] * xj.x, exB[h] * xj.y);
            }
        }
#pragma unroll
        for (int nt = 8; nt < 14; nt++) {
            int off = (nt < 12) ? (nt - 8) * 8 + c * 2
                                : 32 + (nt - 12) * 8 + c * 2;
            if (vA) *reinterpret_cast<float2*>(g_ea23 + (size_t)eeA * 48 + off) =
                        make_float2(D[tt][nt][0], D[tt][nt][1]);
            if (vB) *reinterpret_cast<float2*>(g_ea23 + (size_t)eeB * 48 + off) =
                        make_float2(D[tt][nt][2], D[tt][nt][3]);
        }
    }
}

// ---------------- finish layer1 + project layer2 (16 nodes/block) ------------
__global__ void __launch_bounds__(256) k_node_fin1(
        const float* __restrict__ bias1,
        const float* __restrict__ Wl2, const float* __restrict__ bl2,
        const float* __restrict__ Wr2, const float* __restrict__ br2, int n) {
    __shared__ float sx[16][65];
    int tid = threadIdx.x;
    int nb = blockIdx.x * 16;
#pragma unroll
    for (int i = 0; i < 4; i++) {
        int o = i * 256 + tid;
        int ln = o >> 6, cc = o & 63;
        int node = nb + ln;
        float v = 0.f;
        if (node < n)
            v = g_num1[(size_t)node * 64 + cc] / (g_s1[(size_t)node * 4 + (cc >> 4)] + 1e-16f) + bias1[cc];
        sx[ln][cc] = eluf(v);
    }
    __syncthreads();
    int c = tid & 63, ng = tid >> 6;
    const float* W  = (c < 32) ? Wl2 : Wr2;
    const float* bb = (c < 32) ? bl2 : br2;
    int c2 = c & 31;
    float a[4];
#pragma unroll
    for (int r = 0; r < 4; r++) a[r] = bb[c2];
    for (int k = 0; k < 64; k++) {
        float wv = W[k * 32 + c2];
#pragma unroll
        for (int r = 0; r < 4; r++) a[r] += sx[ng * 4 + r][k] * wv;
    }
#pragma unroll
    for (int r = 0; r < 4; r++) {
        int node = nb + ng * 4 + r;
        if (node < n) {
            if (c < 32) { g_xl[(size_t)node * 32 + c2] = a[r]; g_num2[(size_t)node * 32 + c2] = 0.f; }
            else          g_xr[(size_t)node * 32 + c2] = a[r];
        }
    }
    if (tid < 32) {
        int node = nb + (tid >> 1);
        if (node < n) g_s2[(size_t)node * 2 + (tid & 1)] = 0.f;
    }
}

// ---------------- layer-2 logits + fused softmax accumulation -----------------
__global__ void k_l2(const int* __restrict__ src, const int* __restrict__ dst,
                     const float* __restrict__ att2, int e) {
    int ee = blockIdx.x * 8 + (threadIdx.x >> 5);
    if (ee >= e) return;
    int c = threadIdx.x & 31;
    int s = src[ee], d = dst[ee];
    float xj = g_xl[(size_t)s * 32 + c];
    float ev = leakyr(xj + g_xr[(size_t)d * 32 + c] + g_ea23[(size_t)ee * 48 + c]);
    float p = ev * att2[c];
    p += __shfl_xor_sync(0xFFFFFFFFu, p, 8);
    p += __shfl_xor_sync(0xFFFFFFFFu, p, 4);
    p += __shfl_xor_sync(0xFFFFFFFFu, p, 2);
    p += __shfl_xor_sync(0xFFFFFFFFu, p, 1);
    float ex = expf(p);
    if ((c & 15) == 0) red1(&g_s2[(size_t)d * 2 + (c >> 4)], ex);
    red1(&g_num2[(size_t)d * 32 + c], ex * xj);
}

// ---------------- finish layer2 + project layer3 (16 nodes/block) ------------
__global__ void __launch_bounds__(256) k_node_fin2(
        const float* __restrict__ bias2,
        const float* __restrict__ Wl3, const float* __restrict__ bl3,
        const float* __restrict__ Wr3, const float* __restrict__ br3, int n) {
    __shared__ float sx[16][33];
    int tid = threadIdx.x;
    int nb = blockIdx.x * 16;
#pragma unroll
    for (int i = 0; i < 2; i++) {
        int o = i * 256 + tid;
        int ln = o >> 5, cc = o & 31;
        int node = nb + ln;
        float v = 0.f;
        if (node < n)
            v = g_num2[(size_t)node * 32 + cc] / (g_s2[(size_t)node * 2 + (cc >> 4)] + 1e-16f) + bias2[cc];
        sx[ln][cc] = eluf(v);
    }
    __syncthreads();
    int c = tid & 31, ng = tid >> 5;
    const float* W  = (c < 16) ? Wl3 : Wr3;
    const float* bb = (c < 16) ? bl3 : br3;
    int c2 = c & 15;
    float a[2];
    a[0] = bb[c2]; a[1] = bb[c2];
    for (int k = 0; k < 32; k++) {
        float wv = W[k * 16 + c2];
        a[0] += sx[ng * 2 + 0][k] * wv;
        a[1] += sx[ng * 2 + 1][k] * wv;
    }
#pragma unroll
    for (int r = 0; r < 2; r++) {
        int node = nb + ng * 2 + r;
        if (node < n) {
            if (c < 16) { g_xl[(size_t)node * 16 + c2] = a[r]; g_num3[(size_t)node * 16 + c2] = 0.f; }
            else          g_xr[(size_t)node * 16 + c2] = a[r];
        }
    }
    if (tid < 16) {
        int node = nb + tid;
        if (node < n) g_s3[node] = 0.f;
    }
}

// ---------------- layer-3 logits + fused softmax accumulation -----------------
__global__ void k_l3(const int* __restrict__ src, const int* __restrict__ dst,
                     const float* __restrict__ att3, int e) {
    int ee = blockIdx.x * 8 + (threadIdx.x >> 4);
    int c = threadIdx.x & 15;
    bool ok = ee < e;
    int s = ok ? src[ee] : 0, d = ok ? dst[ee] : 0;
    float xj = ok ? g_xl[(size_t)s * 16 + c] : 0.f;
    float ev = ok ? leakyr(xj + g_xr[(size_t)d * 16 + c] + g_ea23[(size_t)ee * 48 + 32 + c]) : 0.f;
    float p = ev * att3[c];
    p += __shfl_xor_sync(0xFFFFFFFFu, p, 8);
    p += __shfl_xor_sync(0xFFFFFFFFu, p, 4);
    p += __shfl_xor_sync(0xFFFFFFFFu, p, 2);
    p += __shfl_xor_sync(0xFFFFFFFFu, p, 1);
    if (ok) {
        float ex = expf(p);
        if (c == 0) red1(&g_s3[d], ex);
        red1(&g_num3[(size_t)d * 16 + c], ex * xj);
    }
}

// ---------------- finish layer3 ------------------------------------------------
__global__ void k_node_fin3(const float* __restrict__ bias3, int n) {
    int i = blockIdx.x * blockDim.x + threadIdx.x;
    if (i >= n * 16) return;
    g_x3[i] = g_num3[i] / (g_s3[i >> 4] + 1e-16f) + bias3[i & 15];
}

// ---------------- P/Q precompute -----------------------------------------------
__global__ void __launch_bounds__(256) k_pq(const float* __restrict__ W1, int n) {
    __shared__ float w1s[32 * 64];
    __shared__ float x3s[16][17];
    int tid = threadIdx.x;
    int nb = blockIdx.x * 16;
    for (int i = tid; i < 512; i += 256)
        reinterpret_cast<float4*>(w1s)[i] = reinterpret_cast<const float4*>(W1)[i];
    {
        int node = tid >> 4, k = tid & 15;
        x3s[node][k] = (nb + node < n) ? g_x3[(size_t)(nb + node) * 16 + k] : 0.f;
    }
    __syncthreads();
#pragma unroll
    for (int i = 0; i < 8; i++) {
        int o = i * 256 + tid;
        int node = o >> 7, col = o & 127;
        int hh = col >> 6, j = col & 63;
        float acc = 0.f;
#pragma unroll
        for (int k = 0; k < 16; k++) acc += x3s[node][k] * w1s[(hh * 16 + k) * 64 + j];
        if (nb + node < n) {
            if (hh == 0) g_xl[(size_t)(nb + node) * 64 + j] = acc;
            else         g_xr[(size_t)(nb + node) * 64 + j] = acc;
        }
    }
}

// ---------------- edge MLP: 32 edges/block using P/Q ---------------------------
__global__ void __launch_bounds__(256) k_mlp(
        const int* __restrict__ src, const int* __restrict__ dst,
        const float* __restrict__ b1, const float* __restrict__ W2,
        const float* __restrict__ b2, const float* __restrict__ W3,
        const float* __restrict__ b3, float* __restrict__ out, int e) {
    __shared__ float w2s[64 * 32];
    __shared__ float h1s[32][68];
    __shared__ float h2s[32][33];
    __shared__ int   se[32], de[32];
    __shared__ float w3s[32];
    int tid = threadIdx.x;
    int eb = blockIdx.x * 32;

    for (int i = tid; i < 512; i += 256)
        reinterpret_cast<float4*>(w2s)[i] = reinterpret_cast<const float4*>(W2)[i];
    if (tid < 32) {
        int ee = eb + tid;
        se[tid] = (ee < e) ? src[ee] : 0;
        de[tid] = (ee < e) ? dst[ee] : 0;
        w3s[tid] = W3[tid];
    }
    __syncthreads();

#pragma unroll
    for (int i = 0; i < 8; i++) {
        int o = i * 256 + tid;
        int le = o >> 6, j = o & 63;
        float v = g_xl[(size_t)se[le] * 64 + j] + g_xr[(size_t)de[le] * 64 + j] + b1[j];
        h1s[le][j] = fmaxf(v, 0.f);
    }
    __syncthreads();

    if (tid < 128) {
        int j = tid & 31, eg = tid >> 5;
        float acc[8];
#pragma unroll
        for (int r = 0; r < 8; r++) acc[r] = b2[j];
#pragma unroll
        for (int k4 = 0; k4 < 16; k4++) {
            int k = k4 * 4;
            float w0 = w2s[(k + 0) * 32 + j];
            float w1 = w2s[(k + 1) * 32 + j];
            float w2v = w2s[(k + 2) * 32 + j];
            float w3v = w2s[(k + 3) * 32 + j];
#pragma unroll
            for (int r = 0; r < 8; r++) {
                float4 hv = *reinterpret_cast<const float4*>(&h1s[eg * 8 + r][k]);
                acc[r] += hv.x * w0 + hv.y * w1 + hv.z * w2v + hv.w * w3v;
            }
        }
#pragma unroll
        for (int r = 0; r < 8; r++) h2s[eg * 8 + r][j] = fmaxf(acc[r], 0.f);
    }
    __syncthreads();

    if (tid < 32) {
        float p = 0.f;
#pragma unroll
        for (int k = 0; k < 32; k++) p += h2s[tid][k] * w3s[k];
        int ee = eb + tid;
        if (ee < e) out[ee] = p + b3[0];
    }
}

// ---------------- launch --------------------------------------------------------
extern "C" void kernel_launch(void* const* d_in, const int* in_sizes, int n_in,
                              void* d_out, int out_size) {
    const int*   node_ids = (const int*)  d_in[0];
    const int*   eidx     = (const int*)  d_in[1];
    const float* eattr    = (const float*)d_in[2];
    const float* emb      = (const float*)d_in[3];
    const float* l1_Wl   = (const float*)d_in[4];
    const float* l1_bl   = (const float*)d_in[5];
    const float* l1_Wr   = (const float*)d_in[6];
    const float* l1_br   = (const float*)d_in[7];
    const float* l1_We   = (const float*)d_in[8];
    const float* l1_att  = (const float*)d_in[9];
    const float* l1_bias = (const float*)d_in[10];
    const float* l2_Wl   = (const float*)d_in[11];
    const float* l2_bl   = (const float*)d_in[12];
    const float* l2_Wr   = (const float*)d_in[13];
    const float* l2_br   = (const float*)d_in[14];
    const float* l2_We   = (const float*)d_in[15];
    const float* l2_att  = (const float*)d_in[16];
    const float* l2_bias = (const float*)d_in[17];
    const float* l3_Wl   = (const float*)d_in[18];
    const float* l3_bl   = (const float*)d_in[19];
    const float* l3_Wr   = (const float*)d_in[20];
    const float* l3_br   = (const float*)d_in[21];
    const float* l3_We   = (const float*)d_in[22];
    const float* l3_att  = (const float*)d_in[23];
    const float* l3_bias = (const float*)d_in[24];
    const float* mlp_W1  = (const float*)d_in[25];
    const float* mlp_b1  = (const float*)d_in[26];
    const float* mlp_W2  = (const float*)d_in[27];
    const float* mlp_b2  = (const float*)d_in[28];
    const float* mlp_W3  = (const float*)d_in[29];
    const float* mlp_b3  = (const float*)d_in[30];

    int n = in_sizes[0];
    int e = in_sizes[1] / 2;
    const int* src = eidx;
    const int* dst = eidx + e;
    float* out = (float*)d_out;

    static bool attr_set = false;
    if (!attr_set) {
        cudaFuncSetAttribute(k_edge_mma, cudaFuncAttributeMaxDynamicSharedMemorySize, SM_EP_TOTAL);
        attr_set = true;
    }

    // ---- prep + layer 1 (edge GEMM is launch #4 for ncu visibility) ----
    k_prep_w<<<(NCOL * KPAD + 255) / 256, 256>>>(l1_We, l2_We, l3_We);
    k_node1<<<n, 64>>>(node_ids, emb, l1_Wl, l1_bl, l1_Wr, l1_br, n);
    k_init1<<<(n * 64 + 255) / 256, 256>>>(n);
    k_edge_mma<<<(e + 127) / 128, 128, SM_EP_TOTAL>>>(eattr, src, dst, l1_att, e);
    k_node_fin1<<<(n + 15) / 16, 256>>>(l1_bias, l2_Wl, l2_bl, l2_Wr, l2_br, n);

    // ---- layer 2 (logits+softmax fused) ----
    k_l2<<<(e + 7) / 8, 256>>>(src, dst, l2_att, e);
    k_node_fin2<<<(n + 15) / 16, 256>>>(l2_bias, l3_Wl, l3_bl, l3_Wr, l3_br, n);

    // ---- layer 3 (logits+softmax fused) ----
    k_l3<<<(e + 7) / 8, 128>>>(src, dst, l3_att, e);
    k_node_fin3<<<(n * 16 + 255) / 256, 256>>>(l3_bias, n);

    // ---- edge MLP via P/Q ----
    k_pq<<<(n + 15) / 16, 256>>>(mlp_W1, n);
    k_mlp<<<(e + 31) / 32, 256>>>(src, dst, mlp_b1, mlp_W2, mlp_b2,
                                  mlp_W3, mlp_b3, out, e);
}